// round 2
// baseline (speedup 1.0000x reference)
#include <cuda_runtime.h>

// ---------------- model constants ----------------
#define U_DIM 768
#define T_DIM 1024
#define B_DIM 2
#define BT    2048          // B*T
#define E_DIM 8
#define L_DIM 16
#define V_DIM 32000
#define EPS_F 1e-6f

// ---------------- GEMM tiling ----------------
#define BM 64
#define BN 64
#define BK 16
#define TM 8
#define TN 4
#define GEMM_THREADS 128    // (BM/TM)*(BN/TN) = 8*16

// ---------------- scratch (static device memory; no runtime alloc) ----------------
__device__ float g_h0 [BT * U_DIM];
__device__ float g_h  [BT * U_DIM];
__device__ float g_inp[BT * U_DIM];
__device__ float g_n  [BT * U_DIM];
__device__ float g_q  [BT * U_DIM];
__device__ float g_k  [BT * U_DIM];
__device__ float g_v  [BT * U_DIM];
__device__ float g_tmp[BT * U_DIM];
__device__ float g_kv [B_DIM * U_DIM * U_DIM];
__device__ float g_ksum[B_DIM * U_DIM];
__device__ float g_den[BT];
__device__ float g_gate[BT * E_DIM];

// ---------------- helpers ----------------
__device__ __forceinline__ float warpSum(float v) {
    #pragma unroll
    for (int o = 16; o > 0; o >>= 1) v += __shfl_xor_sync(0xffffffffu, v, o);
    return v;
}

// ---------------- generic GEMM with fused epilogues ----------------
// EPI 0: C = acc*scale + bias[n]
// EPI 1: C = phi(acc + bias) = (t>0 ? t+1 : exp(t))          (elu+1)
// EPI 2: C = sigmoid(acc + bias)
// EPI 3: C = sigmoid(acc + bias) + aux1[idx] + aux2[idx]
// EPI 4: C = acc / aux1[row] + aux2[idx]                      (attention num/den + residual)
template<int EPI>
__global__ __launch_bounds__(GEMM_THREADS)
void gemm_kernel(const float* __restrict__ A, const float* __restrict__ B, float* C,
                 int M, int N, int K, int transA,
                 long aStrideZ, long bStrideZ, long cStrideZ,
                 const float* __restrict__ bias, long biasStrideZ,
                 const float* aux1, long aux1StrideZ,
                 const float* aux2, long aux2StrideZ,
                 float scale)
{
    int z = blockIdx.z;
    A += z * aStrideZ;
    B += z * bStrideZ;
    C += z * cStrideZ;
    if (bias) bias += z * biasStrideZ;
    if (aux1) aux1 += z * aux1StrideZ;
    if (aux2) aux2 += z * aux2StrideZ;

    __shared__ float As[BK][BM + 4];
    __shared__ float Bs[BK][BN + 4];

    const int tid = threadIdx.x;
    const int tm  = tid >> 4;     // 0..7
    const int tn  = tid & 15;     // 0..15
    const int row0 = blockIdx.y * BM;
    const int col0 = blockIdx.x * BN;

    float acc[TM][TN];
    #pragma unroll
    for (int i = 0; i < TM; i++)
        #pragma unroll
        for (int j = 0; j < TN; j++) acc[i][j] = 0.f;

    for (int k0 = 0; k0 < K; k0 += BK) {
        if (!transA) {
            // A is [M,K] row-major (lda = K)
            #pragma unroll
            for (int t = 0; t < 2; t++) {
                int idx = tid + t * GEMM_THREADS;  // 0..255
                int r   = idx >> 2;                // 0..63
                int c4  = idx & 3;                 // 0..3
                float4 v4 = *(const float4*)(A + (long)(row0 + r) * K + k0 + c4 * 4);
                As[c4 * 4 + 0][r] = v4.x;
                As[c4 * 4 + 1][r] = v4.y;
                As[c4 * 4 + 2][r] = v4.z;
                As[c4 * 4 + 3][r] = v4.w;
            }
        } else {
            // A is [K,M] row-major (lda = M)
            #pragma unroll
            for (int t = 0; t < 2; t++) {
                int idx = tid + t * GEMM_THREADS;
                int kk  = idx >> 4;                // 0..15
                int m4  = idx & 15;                // 0..15
                float4 v4 = *(const float4*)(A + (long)(k0 + kk) * M + row0 + m4 * 4);
                *(float4*)&As[kk][m4 * 4] = v4;
            }
        }
        // B is [K,N] row-major
        #pragma unroll
        for (int t = 0; t < 2; t++) {
            int idx = tid + t * GEMM_THREADS;
            int kk  = idx >> 4;
            int n4  = idx & 15;
            float4 v4 = *(const float4*)(B + (long)(k0 + kk) * N + col0 + n4 * 4);
            *(float4*)&Bs[kk][n4 * 4] = v4;
        }
        __syncthreads();

        #pragma unroll
        for (int kk = 0; kk < BK; kk++) {
            float ra[TM], rb[TN];
            #pragma unroll
            for (int i = 0; i < TM; i++) ra[i] = As[kk][tm * TM + i];
            #pragma unroll
            for (int j = 0; j < TN; j++) rb[j] = Bs[kk][tn * TN + j];
            #pragma unroll
            for (int i = 0; i < TM; i++)
                #pragma unroll
                for (int j = 0; j < TN; j++)
                    acc[i][j] = fmaf(ra[i], rb[j], acc[i][j]);
        }
        __syncthreads();
    }

    // epilogue
    #pragma unroll
    for (int i = 0; i < TM; i++) {
        int r = row0 + tm * TM + i;
        #pragma unroll
        for (int j = 0; j < TN; j++) {
            int c = col0 + tn * TN + j;
            long idx = (long)r * N + c;
            float a = acc[i][j];
            float b = bias ? bias[c] : 0.f;
            float o;
            if (EPI == 0) {
                o = a * scale + b;
            } else if (EPI == 1) {
                float t = a + b;
                o = (t > 0.f) ? (t + 1.f) : __expf(t);
            } else if (EPI == 2) {
                float t = a + b;
                o = 1.f / (1.f + __expf(-t));
            } else if (EPI == 3) {
                float t = a + b;
                o = 1.f / (1.f + __expf(-t)) + aux1[idx] + aux2[idx];
            } else { // EPI == 4
                o = a / aux1[r] + aux2[idx];
            }
            C[idx] = o;
        }
    }
}

// ---------------- MoE GEMM: h[t,:] = sum_e gate[t,e] * (n @ eW_e + eb_e) ----------------
__global__ __launch_bounds__(GEMM_THREADS)
void moe_kernel(const float* __restrict__ A,      // n [BT,U]
                const float* __restrict__ Bex,    // eW_l [E,U,U]
                const float* __restrict__ ebias,  // eb_l [E,U]
                const float* __restrict__ gate,   // [BT,E]
                float* C,                         // h   [BT,U]
                int M, int N, int K)
{
    __shared__ float As[BK][BM + 4];
    __shared__ float Bs[BK][BN + 4];

    const int tid = threadIdx.x;
    const int tm  = tid >> 4;
    const int tn  = tid & 15;
    const int row0 = blockIdx.y * BM;
    const int col0 = blockIdx.x * BN;

    float total[TM][TN];
    #pragma unroll
    for (int i = 0; i < TM; i++)
        #pragma unroll
        for (int j = 0; j < TN; j++) total[i][j] = 0.f;

    for (int e = 0; e < E_DIM; e++) {
        const float* B = Bex + (long)e * K * N;
        float acc[TM][TN];
        #pragma unroll
        for (int i = 0; i < TM; i++)
            #pragma unroll
            for (int j = 0; j < TN; j++) acc[i][j] = 0.f;

        for (int k0 = 0; k0 < K; k0 += BK) {
            #pragma unroll
            for (int t = 0; t < 2; t++) {
                int idx = tid + t * GEMM_THREADS;
                int r   = idx >> 2;
                int c4  = idx & 3;
                float4 v4 = *(const float4*)(A + (long)(row0 + r) * K + k0 + c4 * 4);
                As[c4 * 4 + 0][r] = v4.x;
                As[c4 * 4 + 1][r] = v4.y;
                As[c4 * 4 + 2][r] = v4.z;
                As[c4 * 4 + 3][r] = v4.w;
            }
            #pragma unroll
            for (int t = 0; t < 2; t++) {
                int idx = tid + t * GEMM_THREADS;
                int kk  = idx >> 4;
                int n4  = idx & 15;
                float4 v4 = *(const float4*)(B + (long)(k0 + kk) * N + col0 + n4 * 4);
                *(float4*)&Bs[kk][n4 * 4] = v4;
            }
            __syncthreads();
            #pragma unroll
            for (int kk = 0; kk < BK; kk++) {
                float ra[TM], rb[TN];
                #pragma unroll
                for (int i = 0; i < TM; i++) ra[i] = As[kk][tm * TM + i];
                #pragma unroll
                for (int j = 0; j < TN; j++) rb[j] = Bs[kk][tn * TN + j];
                #pragma unroll
                for (int i = 0; i < TM; i++)
                    #pragma unroll
                    for (int j = 0; j < TN; j++)
                        acc[i][j] = fmaf(ra[i], rb[j], acc[i][j]);
            }
            __syncthreads();
        }

        #pragma unroll
        for (int i = 0; i < TM; i++) {
            float g = gate[(long)(row0 + tm * TM + i) * E_DIM + e];
            #pragma unroll
            for (int j = 0; j < TN; j++) {
                float bj = ebias[(long)e * N + col0 + tn * TN + j];
                total[i][j] = fmaf(g, acc[i][j] + bj, total[i][j]);
            }
        }
    }

    #pragma unroll
    for (int i = 0; i < TM; i++) {
        int r = row0 + tm * TM + i;
        #pragma unroll
        for (int j = 0; j < TN; j++)
            C[(long)r * N + col0 + tn * TN + j] = total[i][j];
    }
}

// ---------------- small kernels ----------------
__global__ __launch_bounds__(192)
void gather_kernel(const int* __restrict__ x, const float* __restrict__ emb, float* xe)
{
    int row = blockIdx.x;
    int tok = x[row];
    const float4* src = (const float4*)(emb + (long)tok * U_DIM);
    float4* dst = (float4*)(xe + (long)row * U_DIM);
    for (int i = threadIdx.x; i < U_DIM / 4; i += blockDim.x) dst[i] = src[i];
}

__global__ __launch_bounds__(256)
void rms_kernel(const float* __restrict__ h, float* out)
{
    long row = blockIdx.x;
    const float* hr = h + row * U_DIM;
    float s = 0.f;
    for (int u = threadIdx.x; u < U_DIM; u += 256) { float t = hr[u]; s = fmaf(t, t, s); }
    s = warpSum(s);
    __shared__ float red[8];
    __shared__ float rsh;
    int wid = threadIdx.x >> 5, lane = threadIdx.x & 31;
    if (lane == 0) red[wid] = s;
    __syncthreads();
    if (threadIdx.x == 0) {
        float tot = 0.f;
        #pragma unroll
        for (int i = 0; i < 8; i++) tot += red[i];
        rsh = rsqrtf(tot / (float)U_DIM + EPS_F);
    }
    __syncthreads();
    float r = rsh;
    for (int u = threadIdx.x; u < U_DIM; u += 256) out[row * U_DIM + u] = hr[u] * r;
}

__global__ __launch_bounds__(256)
void colsum_kernel(const float* __restrict__ kbuf, float* ks)
{
    int b = blockIdx.y;
    int u = blockIdx.x * 256 + threadIdx.x;
    const float* kb = kbuf + (long)b * T_DIM * U_DIM;
    float s = 0.f;
    for (int t = 0; t < T_DIM; t++) s += kb[(long)t * U_DIM + u];
    ks[b * U_DIM + u] = s;
}

__global__ __launch_bounds__(256)
void den_kernel(const float* __restrict__ q, const float* __restrict__ ks, float* den)
{
    int gwarp = (blockIdx.x * blockDim.x + threadIdx.x) >> 5;
    int lane  = threadIdx.x & 31;
    if (gwarp >= BT) return;
    int b = gwarp / T_DIM;
    const float* qr = q + (long)gwarp * U_DIM;
    const float* kb = ks + b * U_DIM;
    float s = 0.f;
    for (int u = lane; u < U_DIM; u += 32) s = fmaf(qr[u], kb[u], s);
    s = warpSum(s);
    if (lane == 0) den[gwarp] = s + EPS_F;
}

__global__ __launch_bounds__(256)
void gate_kernel(const float* __restrict__ n, const float* __restrict__ gWl,
                 const float* __restrict__ gbl, float* gate)
{
    int row = blockIdx.x;
    int wid = threadIdx.x >> 5, lane = threadIdx.x & 31;
    const float* nr = n + (long)row * U_DIM;
    float s = 0.f;
    for (int u = lane; u < U_DIM; u += 32) s = fmaf(nr[u], gWl[u * E_DIM + wid], s);
    s = warpSum(s);
    __shared__ float sl[E_DIM];
    if (lane == 0) sl[wid] = s + gbl[wid];
    __syncthreads();
    if (threadIdx.x == 0) {
        float mx = sl[0];
        #pragma unroll
        for (int e = 1; e < E_DIM; e++) mx = fmaxf(mx, sl[e]);
        float ex[E_DIM], sum = 0.f;
        #pragma unroll
        for (int e = 0; e < E_DIM; e++) { ex[e] = __expf(sl[e] - mx); sum += ex[e]; }
        float inv = 1.f / sum;
        #pragma unroll
        for (int e = 0; e < E_DIM; e++) gate[(long)row * E_DIM + e] = ex[e] * inv;
    }
}

__global__ __launch_bounds__(256)
void add_kernel(const float* __restrict__ a, const float* __restrict__ b, float* c, int n)
{
    int i = blockIdx.x * blockDim.x + threadIdx.x;
    if (i < n) c[i] = a[i] + b[i];
}

// ---------------- host-side GEMM dispatch ----------------
typedef const float* cfp;
static void gemm(int epi, cfp A, cfp B, float* C, int M, int N, int K,
                 int transA, long az, long bz, long cz, int Z,
                 cfp bias, long biasz, cfp aux1, long a1z, cfp aux2, long a2z,
                 float scale)
{
    dim3 grid(N / BN, M / BM, Z);
    dim3 block(GEMM_THREADS);
    switch (epi) {
    case 0: gemm_kernel<0><<<grid, block>>>(A, B, C, M, N, K, transA, az, bz, cz, bias, biasz, aux1, a1z, aux2, a2z, scale); break;
    case 1: gemm_kernel<1><<<grid, block>>>(A, B, C, M, N, K, transA, az, bz, cz, bias, biasz, aux1, a1z, aux2, a2z, scale); break;
    case 2: gemm_kernel<2><<<grid, block>>>(A, B, C, M, N, K, transA, az, bz, cz, bias, biasz, aux1, a1z, aux2, a2z, scale); break;
    case 3: gemm_kernel<3><<<grid, block>>>(A, B, C, M, N, K, transA, az, bz, cz, bias, biasz, aux1, a1z, aux2, a2z, scale); break;
    case 4: gemm_kernel<4><<<grid, block>>>(A, B, C, M, N, K, transA, az, bz, cz, bias, biasz, aux1, a1z, aux2, a2z, scale); break;
    }
}

// ---------------- entry point ----------------
extern "C" void kernel_launch(void* const* d_in, const int* in_sizes, int n_in,
                              void* d_out, int out_size)
{
    const int*   x    = (const int*)  d_in[0];
    const float* emb  = (const float*)d_in[1];
    const float* W_in = (const float*)d_in[2];
    const float* Wq   = (const float*)d_in[3];
    const float* bq   = (const float*)d_in[4];
    const float* Wk   = (const float*)d_in[5];
    const float* bk   = (const float*)d_in[6];
    const float* Wv   = (const float*)d_in[7];
    const float* bv   = (const float*)d_in[8];
    const float* gW   = (const float*)d_in[9];
    const float* gb   = (const float*)d_in[10];
    const float* eW   = (const float*)d_in[11];
    const float* eb   = (const float*)d_in[12];
    const float* fW1  = (const float*)d_in[13];
    const float* fb1  = (const float*)d_in[14];
    const float* fW2  = (const float*)d_in[15];
    const float* fb2  = (const float*)d_in[16];
    const float* Wlog = (const float*)d_in[17];
    float* out = (float*)d_out;

    float *h0, *h, *inp, *n, *q, *k, *v, *tmp, *kv, *ksum, *den, *gate;
    cudaGetSymbolAddress((void**)&h0,   g_h0);
    cudaGetSymbolAddress((void**)&h,    g_h);
    cudaGetSymbolAddress((void**)&inp,  g_inp);
    cudaGetSymbolAddress((void**)&n,    g_n);
    cudaGetSymbolAddress((void**)&q,    g_q);
    cudaGetSymbolAddress((void**)&k,    g_k);
    cudaGetSymbolAddress((void**)&v,    g_v);
    cudaGetSymbolAddress((void**)&tmp,  g_tmp);
    cudaGetSymbolAddress((void**)&kv,   g_kv);
    cudaGetSymbolAddress((void**)&ksum, g_ksum);
    cudaGetSymbolAddress((void**)&den,  g_den);
    cudaGetSymbolAddress((void**)&gate, g_gate);

    const long TU = (long)T_DIM * U_DIM;
    const long UU = (long)U_DIM * U_DIM;
    const size_t HB = sizeof(float) * (size_t)BT * U_DIM;

    // h0 = emb[x] @ W_in ; h = h0
    gather_kernel<<<BT, 192>>>(x, emb, tmp);
    gemm(0, tmp, W_in, h0, BT, U_DIM, U_DIM, 0, 0, 0, 0, 1,
         nullptr, 0, nullptr, 0, nullptr, 0, 1.f);
    cudaMemcpyAsync(h, h0, HB, cudaMemcpyDeviceToDevice, 0);

    for (int l = 0; l < L_DIM; l++) {
        cfp Wq_l = Wq + (long)l * UU,  bq_l = bq + l * U_DIM;
        cfp Wk_l = Wk + (long)l * UU,  bk_l = bk + l * U_DIM;
        cfp Wv_l = Wv + (long)l * UU,  bv_l = bv + l * U_DIM;
        cfp gW_l = gW + (long)l * U_DIM * E_DIM, gb_l = gb + l * E_DIM;
        cfp eW_l = eW + (long)l * E_DIM * UU,    eb_l = eb + (long)l * E_DIM * U_DIM;
        cfp fW1_l = fW1 + (long)l * UU, fb1_l = fb1 + l * U_DIM;
        cfp fW2_l = fW2 + (long)l * UU, fb2_l = fb2 + l * U_DIM;

        cudaMemcpyAsync(inp, h, HB, cudaMemcpyDeviceToDevice, 0);

        // --- linear attention + residual ---
        rms_kernel<<<BT, 256>>>(h, n);
        gemm(1, n, Wq_l, q, BT, U_DIM, U_DIM, 0, 0, 0, 0, 1, bq_l, 0, nullptr, 0, nullptr, 0, 1.f);
        gemm(1, n, Wk_l, k, BT, U_DIM, U_DIM, 0, 0, 0, 0, 1, bk_l, 0, nullptr, 0, nullptr, 0, 1.f);
        gemm(0, n, Wv_l, v, BT, U_DIM, U_DIM, 0, 0, 0, 0, 1, bv_l, 0, nullptr, 0, nullptr, 0, 1.f);
        // kv[b] = k_b^T @ v_b   (M=U, N=U, K=T, batched over z)
        gemm(0, k, v, kv, U_DIM, U_DIM, T_DIM, 1, TU, TU, UU, B_DIM,
             nullptr, 0, nullptr, 0, nullptr, 0, 1.f);
        colsum_kernel<<<dim3(U_DIM / 256, B_DIM), 256>>>(k, ksum);
        den_kernel<<<BT / 8, 256>>>(q, ksum, den);
        // h = (q @ kv) / den + h   (batched over z)
        gemm(4, q, kv, h, T_DIM, U_DIM, U_DIM, 0, TU, UU, TU, B_DIM,
             nullptr, 0, den, T_DIM, h, TU, 1.f);

        // --- soft MoE (replaces h) ---
        rms_kernel<<<BT, 256>>>(h, n);
        gate_kernel<<<BT, 256>>>(n, gW_l, gb_l, gate);
        moe_kernel<<<dim3(U_DIM / BN, BT / BM), GEMM_THREADS>>>(n, eW_l, eb_l, gate, h,
                                                                BT, U_DIM, U_DIM);

        // --- sigmoid MLP + residual + outer residual ---
        rms_kernel<<<BT, 256>>>(h, n);
        gemm(2, n, fW1_l, tmp, BT, U_DIM, U_DIM, 0, 0, 0, 0, 1, fb1_l, 0, nullptr, 0, nullptr, 0, 1.f);
        // h = sigmoid(tmp @ fW2 + fb2) + h + inp
        gemm(3, tmp, fW2_l, h, BT, U_DIM, U_DIM, 0, 0, 0, 0, 1, fb2_l, 0, h, 0, inp, 0, 1.f);
    }

    // final: h = rms(h) + h0; h = rms(h); out = (h @ Wlog) / TEMP
    rms_kernel<<<BT, 256>>>(h, n);
    add_kernel<<<(BT * U_DIM) / 256, 256>>>(n, h0, h, BT * U_DIM);
    rms_kernel<<<BT, 256>>>(h, n);
    gemm(0, n, Wlog, out, BT, V_DIM, U_DIM, 0, 0, 0, 0, 1,
         nullptr, 0, nullptr, 0, nullptr, 0, 2.0f);
}

// round 5
// speedup vs baseline: 1.5692x; 1.5692x over previous
#include <cuda_runtime.h>
#include <cuda_bf16.h>
#include <cstdint>

#define U_DIM 768
#define T_DIM 1024
#define B_DIM 2
#define BT    2048
#define E_DIM 8
#define L_DIM 16
#define V_DIM 32000
#define EPS_F 1e-6f
#define UU    589824L

// weight arena offsets (elements)
#define OFF_WIN  0L
#define OFF_WQ   (UU)
#define OFF_WK   (OFF_WQ + 16L*UU)
#define OFF_WV   (OFF_WK + 16L*UU)
#define OFF_F1   (OFF_WV + 16L*UU)
#define OFF_F2   (OFF_F1 + 16L*UU)
#define OFF_EW   (OFF_F2 + 16L*UU)
#define OFF_WLOG (OFF_EW + 128L*UU)
#define W_TOTAL  (OFF_WLOG + 32000L*768L)

typedef __nv_bfloat16 bf16;

__device__ bf16 g_whi[W_TOTAL];
__device__ bf16 g_wlo[W_TOTAL];

__device__ float g_h [BT*U_DIM], g_h0[BT*U_DIM], g_inp[BT*U_DIM], g_n[BT*U_DIM];
__device__ float g_q [BT*U_DIM], g_k [BT*U_DIM], g_v  [BT*U_DIM], g_f1[BT*U_DIM];
__device__ float g_kvT[B_DIM*UU];
__device__ float g_ksum[B_DIM*U_DIM], g_den[BT], g_gate[BT*E_DIM];
__device__ bf16 g_nhi[BT*U_DIM],  g_nlo[BT*U_DIM];
__device__ bf16 g_xhi[BT*U_DIM],  g_xlo[BT*U_DIM];
__device__ bf16 g_qhi[BT*U_DIM],  g_qlo[BT*U_DIM];
__device__ bf16 g_kthi[BT*U_DIM], g_ktlo[BT*U_DIM];   // [B][U][T]
__device__ bf16 g_vthi[BT*U_DIM], g_vtlo[BT*U_DIM];   // [B][U][T]
__device__ bf16 g_kvhi[B_DIM*UU], g_kvlo[B_DIM*UU];   // kvT [B][v][u]
__device__ bf16 g_f1hi[BT*U_DIM], g_f1lo[BT*U_DIM];
__device__ bf16 g_amhi[BT*6144L], g_amlo[BT*6144L];

__device__ __forceinline__ uint32_t smem_u32(const void* p) {
    uint32_t a;
    asm("{ .reg .u64 t; cvta.to.shared.u64 t, %1; cvt.u32.u64 %0, t; }" : "=r"(a) : "l"(p));
    return a;
}
__device__ __forceinline__ void split2(float x, bf16& hi, bf16& lo) {
    hi = __float2bfloat16(x);
    lo = __float2bfloat16(x - __bfloat162float(hi));
}

// ---------- mma.sync GEMM: D[m,n] = sum_k A[m,k]*B[n,k], 3xBF16 split-compensated ----------
struct GArgs {
    const bf16 *Ahi, *Alo, *Bhi, *Blo;
    int N, K;
    long aZ, bZ, cZ;
    const float* bias;
    const float* den;  long denZ;
    const float* aux1;
    const float* aux2;
    const float* gate;
    const float* ebias;
    float* outF;
};

#define ROWS 72              // smem row stride in bf16 (144 B)
#define BUFB (128 * ROWS)    // bf16 elems per tile buffer
#define DSM  (4 * BUFB * 2)  // 2 tiles (A,B) x 2 buffers x 2 bytes = 73728

// EPI: 0 phi(+b), 1 acc(+b), 3 attn, 4 moe, 5 sigmoid(+b), 6 sig+res2, 7 x2
template<int EPI>
__global__ __launch_bounds__(256)
void mma_gemm(GArgs g)
{
    extern __shared__ char smem[];
    uint32_t sAu = smem_u32(smem);                 // A: buf0,buf1
    uint32_t sBu = sAu + 2 * BUFB * 2;             // B: buf0,buf1
    const int tid = threadIdx.x, wid = tid >> 5, lane = tid & 31;
    const int wm = wid >> 2, wn = wid & 3;         // warp grid 2 x 4
    const int z = blockIdx.z;
    const int row0 = blockIdx.y * 128, col0 = blockIdx.x * 128;
    const int Nn = g.N, K = g.K;

    const bf16* Ahi = g.Ahi + (long)z * g.aZ;
    const bf16* Alo = g.Alo + (long)z * g.aZ;
    const bf16* Bhi = g.Bhi + (long)z * g.bZ;
    const bf16* Blo = g.Blo + (long)z * g.bZ;
    const bf16* Aseg[3] = {Ahi, Ahi, Alo};
    const bf16* Bseg[3] = {Bhi, Blo, Bhi};
    const int CH = K >> 6, C = 3 * CH;

    float d[4][4][4];
    #pragma unroll
    for (int a = 0; a < 4; a++)
        #pragma unroll
        for (int b = 0; b < 4; b++)
            #pragma unroll
            for (int c = 0; c < 4; c++) d[a][b][c] = 0.f;

    // issue cp.async loads for chunk c into buffer buf
    auto issue = [&](int c, int buf) {
        int seg = c / CH;
        int k0  = (c - seg * CH) << 6;
        const bf16* As = Aseg[seg] + (long)row0 * K + k0;
        const bf16* Bs = Bseg[seg] + (long)col0 * K + k0;
        uint32_t da = sAu + buf * BUFB * 2;
        uint32_t db = sBu + buf * BUFB * 2;
        #pragma unroll
        for (int i = 0; i < 4; i++) {
            int idx = tid + (i << 8);        // 0..1023
            int r = idx >> 3, cc = idx & 7;  // row, 16B-chunk
            uint32_t doff = (uint32_t)(r * ROWS + cc * 8) * 2;
            const void* sa = As + (long)r * K + cc * 8;
            asm volatile("cp.async.cg.shared.global [%0], [%1], 16;" :: "r"(da + doff), "l"(sa));
            const void* sb = Bs + (long)r * K + cc * 8;
            asm volatile("cp.async.cg.shared.global [%0], [%1], 16;" :: "r"(db + doff), "l"(sb));
        }
        asm volatile("cp.async.commit_group;");
    };

    issue(0, 0);
    for (int c = 0; c < C; c++) {
        int buf = c & 1;
        if (c + 1 < C) {
            issue(c + 1, buf ^ 1);
            asm volatile("cp.async.wait_group 1;");
        } else {
            asm volatile("cp.async.wait_group 0;");
        }
        __syncthreads();

        uint32_t baseA = sAu + buf * BUFB * 2;
        uint32_t baseB = sBu + buf * BUFB * 2;
        #pragma unroll
        for (int ks = 0; ks < 4; ks++) {
            int k16 = ks * 16;
            uint32_t af[4][4], bfr[4][2];
            #pragma unroll
            for (int mt = 0; mt < 4; mt++) {
                int r = wm * 64 + mt * 16 + (lane & 15);
                uint32_t addr = baseA + (uint32_t)(r * ROWS + k16 + ((lane >> 4) << 3)) * 2;
                asm volatile("ldmatrix.sync.aligned.m8n8.x4.shared.b16 {%0,%1,%2,%3}, [%4];"
                    : "=r"(af[mt][0]), "=r"(af[mt][1]), "=r"(af[mt][2]), "=r"(af[mt][3])
                    : "r"(addr));
            }
            #pragma unroll
            for (int nt = 0; nt < 4; nt++) {
                int nrow = wn * 32 + nt * 8 + (lane & 7);
                int koff = k16 + ((lane >> 3) & 1) * 8;
                uint32_t addr = baseB + (uint32_t)(nrow * ROWS + koff) * 2;
                asm volatile("ldmatrix.sync.aligned.m8n8.x2.shared.b16 {%0,%1}, [%2];"
                    : "=r"(bfr[nt][0]), "=r"(bfr[nt][1]) : "r"(addr));
            }
            #pragma unroll
            for (int mt = 0; mt < 4; mt++)
                #pragma unroll
                for (int nt = 0; nt < 4; nt++)
                    asm volatile("mma.sync.aligned.m16n8k16.row.col.f32.bf16.bf16.f32 "
                        "{%0,%1,%2,%3}, {%4,%5,%6,%7}, {%8,%9}, {%0,%1,%2,%3};"
                        : "+f"(d[mt][nt][0]), "+f"(d[mt][nt][1]),
                          "+f"(d[mt][nt][2]), "+f"(d[mt][nt][3])
                        : "r"(af[mt][0]), "r"(af[mt][1]), "r"(af[mt][2]), "r"(af[mt][3]),
                          "r"(bfr[nt][0]), "r"(bfr[nt][1]));
        }
        __syncthreads();
    }

    // ---------------- epilogue ----------------
    float* outF = g.outF + (long)z * g.cZ;
    #pragma unroll
    for (int mt = 0; mt < 4; mt++) {
        int r0 = row0 + wm * 64 + mt * 16 + (lane >> 2);
        int r1 = r0 + 8;
        float dn0 = 1.f, dn1 = 1.f;
        if (EPI == 3) {
            const float* dz = g.den + (long)z * g.denZ;
            dn0 = dz[r0]; dn1 = dz[r1];
        }
        float gv0[8], gv1[8];
        if (EPI == 4) {
            #pragma unroll
            for (int e = 0; e < 8; e++) {
                gv0[e] = __ldg(&g.gate[(long)r0 * 8 + e]);
                gv1[e] = __ldg(&g.gate[(long)r1 * 8 + e]);
            }
        }
        #pragma unroll
        for (int nt = 0; nt < 4; nt++) {
            int c0 = col0 + wn * 32 + nt * 8 + 2 * (lane & 3);
            #pragma unroll
            for (int half = 0; half < 2; half++) {
                int rg = half ? r1 : r0;
                float dn = half ? dn1 : dn0;
                const float* gv = half ? gv1 : gv0;
                #pragma unroll
                for (int jj = 0; jj < 2; jj++) {
                    int col = c0 + jj;
                    float x = d[mt][nt][half * 2 + jj];
                    long idx = (long)rg * Nn + col;
                    float o;
                    if (EPI == 0) {
                        float t = x + __ldg(&g.bias[col]);
                        o = (t > 0.f) ? (t + 1.f) : __expf(t);
                    } else if (EPI == 1) {
                        float bv = g.bias ? __ldg(&g.bias[col]) : 0.f;
                        o = x + bv;
                    } else if (EPI == 3) {
                        o = x / dn + outF[idx];
                    } else if (EPI == 4) {
                        float bm = 0.f;
                        #pragma unroll
                        for (int e = 0; e < 8; e++)
                            bm = fmaf(gv[e], __ldg(&g.ebias[e * Nn + col]), bm);
                        o = x + bm;
                    } else if (EPI == 5) {
                        float t = x + __ldg(&g.bias[col]);
                        o = 1.f / (1.f + __expf(-t));
                    } else if (EPI == 6) {
                        float t = x + __ldg(&g.bias[col]);
                        o = 1.f / (1.f + __expf(-t)) + g.aux1[idx] + g.aux2[idx];
                    } else {
                        o = x * 2.0f;
                    }
                    outF[idx] = o;
                }
            }
        }
    }
}

// ---------- prepack: dst[n,k] = split(src[k,n]) ----------
__global__ __launch_bounds__(256)
void tsplit(const float* __restrict__ src, bf16* dhi, bf16* dlo, int K, int N, int moe)
{
    __shared__ float t[32][33];
    int z = blockIdx.z;
    const float* s = src + (long)z * K * N;
    long dbase; int dld;
    if (moe) { int l = z >> 3, e = z & 7; dbase = (long)l * 8 * UU + (long)e * U_DIM; dld = 6144; }
    else { dbase = (long)z * K * N; dld = K; }
    int n0 = blockIdx.x * 32, k0 = blockIdx.y * 32;
    int tx = threadIdx.x & 31, ty = threadIdx.x >> 5;
    #pragma unroll
    for (int i = 0; i < 32; i += 8) t[ty + i][tx] = s[(long)(k0 + ty + i) * N + n0 + tx];
    __syncthreads();
    #pragma unroll
    for (int i = 0; i < 32; i += 8) {
        float v = t[tx][ty + i];
        bf16 hi, lo; split2(v, hi, lo);
        long di = dbase + (long)(n0 + ty + i) * dld + k0 + tx;
        dhi[di] = hi; dlo[di] = lo;
    }
}

// ---------- small kernels ----------
__device__ __forceinline__ float warpSum(float v) {
    #pragma unroll
    for (int o = 16; o > 0; o >>= 1) v += __shfl_xor_sync(0xffffffffu, v, o);
    return v;
}
__global__ __launch_bounds__(192)
void gather_split(const int* __restrict__ x, const float* __restrict__ emb, bf16* xhi, bf16* xlo)
{
    int row = blockIdx.x, tok = x[row];
    const float* s = emb + (long)tok * U_DIM;
    for (int i = threadIdx.x; i < U_DIM; i += 192) {
        bf16 hi, lo; split2(s[i], hi, lo);
        xhi[(long)row * U_DIM + i] = hi; xlo[(long)row * U_DIM + i] = lo;
    }
}
__global__ __launch_bounds__(256)
void rms_split(const float* __restrict__ h, float* n, bf16* nhi, bf16* nlo)
{
    long row = blockIdx.x;
    const float* hr = h + row * U_DIM;
    float s = 0.f;
    for (int u = threadIdx.x; u < U_DIM; u += 256) { float t = hr[u]; s = fmaf(t, t, s); }
    s = warpSum(s);
    __shared__ float red[8]; __shared__ float rsh;
    int wid = threadIdx.x >> 5, lane = threadIdx.x & 31;
    if (lane == 0) red[wid] = s;
    __syncthreads();
    if (threadIdx.x == 0) {
        float tot = 0.f;
        #pragma unroll
        for (int i = 0; i < 8; i++) tot += red[i];
        rsh = rsqrtf(tot / (float)U_DIM + EPS_F);
    }
    __syncthreads();
    float r = rsh;
    for (int u = threadIdx.x; u < U_DIM; u += 256) {
        float o = hr[u] * r;
        if (n) n[row * U_DIM + u] = o;
        bf16 hi, lo; split2(o, hi, lo);
        nhi[row * U_DIM + u] = hi; nlo[row * U_DIM + u] = lo;
    }
}
__global__ __launch_bounds__(256)
void splitk(const float* __restrict__ s, bf16* hi, bf16* lo, long n)
{
    long i = (long)blockIdx.x * 256 + threadIdx.x;
    if (i < n) { bf16 h, l; split2(s[i], h, l); hi[i] = h; lo[i] = l; }
}
__global__ __launch_bounds__(256)
void gatemul(const float* __restrict__ n, const float* __restrict__ gate, bf16* hi, bf16* lo)
{
    long i = (long)blockIdx.x * 256 + threadIdx.x;   // BT*6144
    int t = (int)(i / 6144), r = (int)(i % 6144);
    int e = r / 768, u = r % 768;
    float v = gate[(long)t * 8 + e] * n[(long)t * 768 + u];
    bf16 h, l; split2(v, h, l); hi[i] = h; lo[i] = l;
}
__global__ __launch_bounds__(256)
void colsum(const float* __restrict__ kb, float* ks)
{
    int b = blockIdx.y;
    int u = blockIdx.x * 256 + threadIdx.x;
    const float* p = kb + (long)b * T_DIM * U_DIM;
    float s = 0.f;
    for (int t = 0; t < T_DIM; t++) s += p[(long)t * U_DIM + u];
    ks[b * U_DIM + u] = s;
}
__global__ __launch_bounds__(256)
void denk(const float* __restrict__ q, const float* __restrict__ ks, float* den)
{
    int gw = (blockIdx.x * 256 + threadIdx.x) >> 5;
    int lane = threadIdx.x & 31;
    if (gw >= BT) return;
    int b = gw >> 10;
    const float* qr = q + (long)gw * U_DIM;
    const float* kb = ks + b * U_DIM;
    float s = 0.f;
    for (int u = lane; u < U_DIM; u += 32) s = fmaf(qr[u], kb[u], s);
    s = warpSum(s);
    if (lane == 0) den[gw] = s + EPS_F;
}
__global__ __launch_bounds__(256)
void gatek(const float* __restrict__ n, const float* __restrict__ gWl,
           const float* __restrict__ gbl, float* gate)
{
    int row = blockIdx.x;
    int wid = threadIdx.x >> 5, lane = threadIdx.x & 31;
    const float* nr = n + (long)row * U_DIM;
    float s = 0.f;
    for (int u = lane; u < U_DIM; u += 32) s = fmaf(nr[u], gWl[u * E_DIM + wid], s);
    s = warpSum(s);
    __shared__ float sl[E_DIM];
    if (lane == 0) sl[wid] = s + gbl[wid];
    __syncthreads();
    if (threadIdx.x == 0) {
        float mx = sl[0];
        #pragma unroll
        for (int e = 1; e < E_DIM; e++) mx = fmaxf(mx, sl[e]);
        float ex[E_DIM], sum = 0.f;
        #pragma unroll
        for (int e = 0; e < E_DIM; e++) { ex[e] = __expf(sl[e] - mx); sum += ex[e]; }
        float inv = 1.f / sum;
        #pragma unroll
        for (int e = 0; e < E_DIM; e++) gate[(long)row * E_DIM + e] = ex[e] * inv;
    }
}
__global__ __launch_bounds__(256)
void addk(const float* __restrict__ a, const float* __restrict__ b, float* c, int n)
{
    int i = blockIdx.x * 256 + threadIdx.x;
    if (i < n) c[i] = a[i] + b[i];
}

// ---------- host dispatch ----------
static void tc(int epi, GArgs& a, int M, int N, int Z)
{
    dim3 g(N / 128, M / 128, Z);
    switch (epi) {
    case 0: mma_gemm<0><<<g, 256, DSM>>>(a); break;
    case 1: mma_gemm<1><<<g, 256, DSM>>>(a); break;
    case 3: mma_gemm<3><<<g, 256, DSM>>>(a); break;
    case 4: mma_gemm<4><<<g, 256, DSM>>>(a); break;
    case 5: mma_gemm<5><<<g, 256, DSM>>>(a); break;
    case 6: mma_gemm<6><<<g, 256, DSM>>>(a); break;
    case 7: mma_gemm<7><<<g, 256, DSM>>>(a); break;
    }
}

extern "C" void kernel_launch(void* const* d_in, const int* in_sizes, int n_in,
                              void* d_out, int out_size)
{
    const int*   x    = (const int*)  d_in[0];
    const float* emb  = (const float*)d_in[1];
    const float* W_in = (const float*)d_in[2];
    const float* Wq   = (const float*)d_in[3];
    const float* bq   = (const float*)d_in[4];
    const float* Wk   = (const float*)d_in[5];
    const float* bk   = (const float*)d_in[6];
    const float* Wv   = (const float*)d_in[7];
    const float* bv   = (const float*)d_in[8];
    const float* gW   = (const float*)d_in[9];
    const float* gb   = (const float*)d_in[10];
    const float* eW   = (const float*)d_in[11];
    const float* eb   = (const float*)d_in[12];
    const float* fW1  = (const float*)d_in[13];
    const float* fb1  = (const float*)d_in[14];
    const float* fW2  = (const float*)d_in[15];
    const float* fb2  = (const float*)d_in[16];
    const float* Wlog = (const float*)d_in[17];
    float* out = (float*)d_out;

    cudaFuncSetAttribute(mma_gemm<0>, cudaFuncAttributeMaxDynamicSharedMemorySize, DSM);
    cudaFuncSetAttribute(mma_gemm<1>, cudaFuncAttributeMaxDynamicSharedMemorySize, DSM);
    cudaFuncSetAttribute(mma_gemm<3>, cudaFuncAttributeMaxDynamicSharedMemorySize, DSM);
    cudaFuncSetAttribute(mma_gemm<4>, cudaFuncAttributeMaxDynamicSharedMemorySize, DSM);
    cudaFuncSetAttribute(mma_gemm<5>, cudaFuncAttributeMaxDynamicSharedMemorySize, DSM);
    cudaFuncSetAttribute(mma_gemm<6>, cudaFuncAttributeMaxDynamicSharedMemorySize, DSM);
    cudaFuncSetAttribute(mma_gemm<7>, cudaFuncAttributeMaxDynamicSharedMemorySize, DSM);

    bf16 *whi, *wlo;
    float *h, *h0, *inp, *n, *q, *k, *v, *f1, *kvT, *ksum, *den, *gate;
    bf16 *nhi, *nlo, *xhi, *xlo, *qhi, *qlo, *kthi, *ktlo, *vthi, *vtlo;
    bf16 *kvhi, *kvlo, *f1hi, *f1lo, *amhi, *amlo;
    cudaGetSymbolAddress((void**)&whi, g_whi);  cudaGetSymbolAddress((void**)&wlo, g_wlo);
    cudaGetSymbolAddress((void**)&h, g_h);      cudaGetSymbolAddress((void**)&h0, g_h0);
    cudaGetSymbolAddress((void**)&inp, g_inp);  cudaGetSymbolAddress((void**)&n, g_n);
    cudaGetSymbolAddress((void**)&q, g_q);      cudaGetSymbolAddress((void**)&k, g_k);
    cudaGetSymbolAddress((void**)&v, g_v);      cudaGetSymbolAddress((void**)&f1, g_f1);
    cudaGetSymbolAddress((void**)&kvT, g_kvT);  cudaGetSymbolAddress((void**)&ksum, g_ksum);
    cudaGetSymbolAddress((void**)&den, g_den);  cudaGetSymbolAddress((void**)&gate, g_gate);
    cudaGetSymbolAddress((void**)&nhi, g_nhi);  cudaGetSymbolAddress((void**)&nlo, g_nlo);
    cudaGetSymbolAddress((void**)&xhi, g_xhi);  cudaGetSymbolAddress((void**)&xlo, g_xlo);
    cudaGetSymbolAddress((void**)&qhi, g_qhi);  cudaGetSymbolAddress((void**)&qlo, g_qlo);
    cudaGetSymbolAddress((void**)&kthi, g_kthi); cudaGetSymbolAddress((void**)&ktlo, g_ktlo);
    cudaGetSymbolAddress((void**)&vthi, g_vthi); cudaGetSymbolAddress((void**)&vtlo, g_vtlo);
    cudaGetSymbolAddress((void**)&kvhi, g_kvhi); cudaGetSymbolAddress((void**)&kvlo, g_kvlo);
    cudaGetSymbolAddress((void**)&f1hi, g_f1hi); cudaGetSymbolAddress((void**)&f1lo, g_f1lo);
    cudaGetSymbolAddress((void**)&amhi, g_amhi); cudaGetSymbolAddress((void**)&amlo, g_amlo);

    const long TU = (long)T_DIM * U_DIM;
    const size_t HB = sizeof(float) * (size_t)BT * U_DIM;

    // ---- weight prepack: transpose+split into arena ----
    tsplit<<<dim3(24, 24, 1),   256>>>(W_in, whi + OFF_WIN, wlo + OFF_WIN, 768, 768, 0);
    tsplit<<<dim3(24, 24, 16),  256>>>(Wq,   whi + OFF_WQ,  wlo + OFF_WQ,  768, 768, 0);
    tsplit<<<dim3(24, 24, 16),  256>>>(Wk,   whi + OFF_WK,  wlo + OFF_WK,  768, 768, 0);
    tsplit<<<dim3(24, 24, 16),  256>>>(Wv,   whi + OFF_WV,  wlo + OFF_WV,  768, 768, 0);
    tsplit<<<dim3(24, 24, 16),  256>>>(fW1,  whi + OFF_F1,  wlo + OFF_F1,  768, 768, 0);
    tsplit<<<dim3(24, 24, 16),  256>>>(fW2,  whi + OFF_F2,  wlo + OFF_F2,  768, 768, 0);
    tsplit<<<dim3(24, 24, 128), 256>>>(eW,   whi + OFF_EW,  wlo + OFF_EW,  768, 768, 1);
    tsplit<<<dim3(1000, 24, 1), 256>>>(Wlog, whi + OFF_WLOG, wlo + OFF_WLOG, 768, 32000, 0);

    GArgs a = {};

    // ---- h0 = emb[x] @ W_in ----
    gather_split<<<BT, 192>>>(x, emb, xhi, xlo);
    a = {xhi, xlo, whi + OFF_WIN, wlo + OFF_WIN, 768, 768, 0, 0, 0,
         nullptr, nullptr, 0, nullptr, nullptr, nullptr, nullptr, h0};
    tc(1, a, BT, 768, 1);
    cudaMemcpyAsync(h, h0, HB, cudaMemcpyDeviceToDevice, 0);

    for (int l = 0; l < L_DIM; l++) {
        const bf16 *wq_h = whi + OFF_WQ + l * UU, *wq_l = wlo + OFF_WQ + l * UU;
        const bf16 *wk_h = whi + OFF_WK + l * UU, *wk_l = wlo + OFF_WK + l * UU;
        const bf16 *wv_h = whi + OFF_WV + l * UU, *wv_l = wlo + OFF_WV + l * UU;
        const bf16 *f1_h = whi + OFF_F1 + l * UU, *f1_l = wlo + OFF_F1 + l * UU;
        const bf16 *f2_h = whi + OFF_F2 + l * UU, *f2_l = wlo + OFF_F2 + l * UU;
        const bf16 *ew_h = whi + OFF_EW + l * 8 * UU, *ew_l = wlo + OFF_EW + l * 8 * UU;

        cudaMemcpyAsync(inp, h, HB, cudaMemcpyDeviceToDevice, 0);

        // --- linear attention ---
        rms_split<<<BT, 256>>>(h, n, nhi, nlo);
        a = {nhi, nlo, wq_h, wq_l, 768, 768, 0, 0, 0, bq + l * U_DIM,
             nullptr, 0, nullptr, nullptr, nullptr, nullptr, q};
        tc(0, a, BT, 768, 1);
        a.Bhi = wk_h; a.Blo = wk_l; a.bias = bk + l * U_DIM; a.outF = k;
        tc(0, a, BT, 768, 1);
        a.Bhi = wv_h; a.Blo = wv_l; a.bias = bv + l * U_DIM; a.outF = v;
        tc(1, a, BT, 768, 1);
        splitk<<<(BT * U_DIM) / 256, 256>>>(q, qhi, qlo, (long)BT * U_DIM);
        tsplit<<<dim3(24, 32, 2), 256>>>(k, kthi, ktlo, 1024, 768, 0);
        tsplit<<<dim3(24, 32, 2), 256>>>(v, vthi, vtlo, 1024, 768, 0);
        // kvT[b][v][u] = sum_t v[t,v]*k[t,u]
        a = {vthi, vtlo, kthi, ktlo, 768, 1024, TU, TU, UU,
             nullptr, nullptr, 0, nullptr, nullptr, nullptr, nullptr, kvT};
        tc(1, a, 768, 768, 2);
        splitk<<<(2 * (int)UU) / 256, 256>>>(kvT, kvhi, kvlo, 2 * UU);
        colsum<<<dim3(3, 2), 256>>>(k, ksum);
        denk<<<256, 256>>>(q, ksum, den);
        // h = (q @ kv) / den + h
        a = {qhi, qlo, kvhi, kvlo, 768, 768, TU, UU, TU,
             nullptr, den, T_DIM, nullptr, nullptr, nullptr, nullptr, h};
        tc(3, a, T_DIM, 768, 2);

        // --- soft MoE ---
        rms_split<<<BT, 256>>>(h, n, nhi, nlo);
        gatek<<<BT, 256>>>(n, gW + (long)l * U_DIM * E_DIM, gb + l * E_DIM, gate);
        gatemul<<<(BT * 6144) / 256, 256>>>(n, gate, amhi, amlo);
        a = {amhi, amlo, ew_h, ew_l, 768, 6144, 0, 0, 0,
             nullptr, nullptr, 0, nullptr, nullptr, gate, eb + (long)l * E_DIM * U_DIM, h};
        tc(4, a, BT, 768, 1);

        // --- FFN + residuals ---
        rms_split<<<BT, 256>>>(h, n, nhi, nlo);
        a = {nhi, nlo, f1_h, f1_l, 768, 768, 0, 0, 0, fb1 + l * U_DIM,
             nullptr, 0, nullptr, nullptr, nullptr, nullptr, f1};
        tc(5, a, BT, 768, 1);
        splitk<<<(BT * U_DIM) / 256, 256>>>(f1, f1hi, f1lo, (long)BT * U_DIM);
        a = {f1hi, f1lo, f2_h, f2_l, 768, 768, 0, 0, 0, fb2 + l * U_DIM,
             nullptr, 0, h, inp, nullptr, nullptr, h};
        tc(6, a, BT, 768, 1);
    }

    // ---- final norms + logits ----
    rms_split<<<BT, 256>>>(h, n, nhi, nlo);
    addk<<<(BT * U_DIM) / 256, 256>>>(n, h0, h, BT * U_DIM);
    rms_split<<<BT, 256>>>(h, nullptr, nhi, nlo);
    a = {nhi, nlo, whi + OFF_WLOG, wlo + OFF_WLOG, 32000, 768, 0, 0, 0,
         nullptr, nullptr, 0, nullptr, nullptr, nullptr, nullptr, out};
    tc(7, a, BT, 32000, 1);
}

// round 6
// speedup vs baseline: 1.9651x; 1.2523x over previous
#include <cuda_runtime.h>
#include <cuda_bf16.h>
#include <cstdint>

#define U_DIM 768
#define T_DIM 1024
#define B_DIM 2
#define BT    2048
#define E_DIM 8
#define L_DIM 16
#define V_DIM 32000
#define EPS_F 1e-6f
#define UU    589824L

// weight arena offsets (elements)
#define OFF_WIN  0L
#define OFF_QKV  (UU)                    // 16 layers x [2304 x 768]
#define OFF_F1   (OFF_QKV + 48L*UU)
#define OFF_F2   (OFF_F1 + 16L*UU)
#define OFF_EW   (OFF_F2 + 16L*UU)
#define OFF_WLOG (OFF_EW + 128L*UU)
#define W_TOTAL  (OFF_WLOG + 32000L*768L)

typedef __nv_bfloat16 bf16;

__device__ bf16 g_whi[W_TOTAL];
__device__ bf16 g_wlo[W_TOTAL];

__device__ float g_h [BT*U_DIM], g_h0[BT*U_DIM], g_hA[BT*U_DIM], g_hM[BT*U_DIM];
__device__ float g_n [BT*U_DIM];
__device__ float g_q [BT*U_DIM], g_k [BT*U_DIM], g_v [BT*U_DIM];
__device__ float g_mo[2L*BT*U_DIM];                   // moe split-K partials
__device__ float g_ksum[B_DIM*U_DIM], g_den[BT], g_gate[BT*E_DIM];
__device__ bf16 g_nhi[BT*U_DIM],  g_nlo[BT*U_DIM];
__device__ bf16 g_xhi[BT*U_DIM],  g_xlo[BT*U_DIM];
__device__ bf16 g_qhi[BT*U_DIM],  g_qlo[BT*U_DIM];
__device__ bf16 g_kthi[BT*U_DIM], g_ktlo[BT*U_DIM];   // [B][U][T]
__device__ bf16 g_vthi[BT*U_DIM], g_vtlo[BT*U_DIM];   // [B][U][T]
__device__ bf16 g_kvhi[B_DIM*UU], g_kvlo[B_DIM*UU];   // kvT [B][v][u]
__device__ bf16 g_f1hi[BT*U_DIM], g_f1lo[BT*U_DIM];
__device__ bf16 g_amhi[BT*6144L], g_amlo[BT*6144L];

__device__ __forceinline__ uint32_t smem_u32(const void* p) {
    uint32_t a;
    asm("{ .reg .u64 t; cvta.to.shared.u64 t, %1; cvt.u32.u64 %0, t; }" : "=r"(a) : "l"(p));
    return a;
}
__device__ __forceinline__ void split2(float x, bf16& hi, bf16& lo) {
    hi = __float2bfloat16(x);
    lo = __float2bfloat16(x - __bfloat162float(hi));
}

// ---------- mma.sync GEMM: D[m,n] = sum_k A[m,k]*B[n,k], 3xBF16 split-compensated ----------
struct GArgs {
    const bf16 *Ahi, *Alo, *Bhi, *Blo;
    int N, K, kSplit;
    long aZ, bZ, cZ, a1Z;
    const float *bias, *bias2, *bias3;
    const float *den;  long denZ;
    const float *aux1, *aux2;
    const float *gate, *ebias;
    float *outF, *outF2, *outF3;
    bf16 *oHi, *oLo;
};

#define ROWS 72                   // smem row stride in bf16 (144 B)
#define TB   (128 * ROWS * 2)     // bytes per tile = 18432
#define DSM  (8 * TB)             // 2 stages x 4 tiles = 147456

// EPI: 1 acc(+b)[+copy2], 3 attn, 4 moe-partial, 6 sig+res2, 7 x2,
//      8 qkv, 9 split-out, 10 sigmoid-split
template<int EPI>
__global__ __launch_bounds__(256)
void mma_gemm(GArgs g)
{
    extern __shared__ char smem[];
    uint32_t sb = smem_u32(smem);
    const int tid = threadIdx.x, wid = tid >> 5, lane = tid & 31;
    const int wm = wid >> 2, wn = wid & 3;        // warp grid 2 x 4
    const int z = blockIdx.z;
    const int row0 = blockIdx.y * 128, col0 = blockIdx.x * 128;
    const int Nn = g.N, K = g.K;

    const bf16* Ahi = g.Ahi + (long)z * g.aZ;
    const bf16* Alo = g.Alo + (long)z * g.aZ;
    const bf16* Bhi = g.Bhi + (long)z * g.bZ;
    const bf16* Blo = g.Blo + (long)z * g.bZ;
    const int kbase = g.kSplit ? z * g.kSplit : 0;
    const int CH = (g.kSplit ? g.kSplit : K) >> 6;

    float d[4][4][4];
    #pragma unroll
    for (int a = 0; a < 4; a++)
        #pragma unroll
        for (int b = 0; b < 4; b++)
            #pragma unroll
            for (int c = 0; c < 4; c++) d[a][b][c] = 0.f;

    // load 4 tiles (AH, AL, BH, BL) for chunk c into stage s
    auto issue = [&](int c, int s) {
        int k0 = kbase + (c << 6);
        const bf16* srcs[4] = {
            Ahi + (long)row0 * K + k0, Alo + (long)row0 * K + k0,
            Bhi + (long)col0 * K + k0, Blo + (long)col0 * K + k0 };
        #pragma unroll
        for (int t = 0; t < 4; t++) {
            uint32_t dst = sb + (uint32_t)(s * 4 + t) * TB;
            #pragma unroll
            for (int i = 0; i < 4; i++) {
                int idx = tid + (i << 8);
                int r = idx >> 3, cc = idx & 7;
                uint32_t doff = (uint32_t)(r * ROWS + cc * 8) * 2;
                const void* sp = srcs[t] + (long)r * K + cc * 8;
                asm volatile("cp.async.cg.shared.global [%0], [%1], 16;"
                             :: "r"(dst + doff), "l"(sp));
            }
        }
        asm volatile("cp.async.commit_group;");
    };

    issue(0, 0);
    for (int c = 0; c < CH; c++) {
        int s = c & 1;
        if (c + 1 < CH) {
            issue(c + 1, s ^ 1);
            asm volatile("cp.async.wait_group 1;");
        } else {
            asm volatile("cp.async.wait_group 0;");
        }
        __syncthreads();

        uint32_t bAH = sb + (uint32_t)(s * 4 + 0) * TB;
        uint32_t bAL = sb + (uint32_t)(s * 4 + 1) * TB;
        uint32_t bBH = sb + (uint32_t)(s * 4 + 2) * TB;
        uint32_t bBL = sb + (uint32_t)(s * 4 + 3) * TB;

        #pragma unroll
        for (int ks = 0; ks < 4; ks++) {
            int k16 = ks * 16;
            int aoff = (wm * 64 + (lane & 15)) * ROWS + k16 + ((lane >> 4) << 3);
            int boff = (wn * 32 + (lane & 7)) * ROWS + k16 + (((lane >> 3) & 1) << 3);
            uint32_t af[4][4], bf_[4][2];

            #pragma unroll
            for (int mt = 0; mt < 4; mt++) {
                uint32_t ad = bAH + (uint32_t)(aoff + mt * 16 * ROWS) * 2;
                asm volatile("ldmatrix.sync.aligned.m8n8.x4.shared.b16 {%0,%1,%2,%3}, [%4];"
                    : "=r"(af[mt][0]), "=r"(af[mt][1]), "=r"(af[mt][2]), "=r"(af[mt][3])
                    : "r"(ad));
            }
            #pragma unroll
            for (int nt = 0; nt < 4; nt++) {
                uint32_t bd = bBH + (uint32_t)(boff + nt * 8 * ROWS) * 2;
                asm volatile("ldmatrix.sync.aligned.m8n8.x2.shared.b16 {%0,%1}, [%2];"
                    : "=r"(bf_[nt][0]), "=r"(bf_[nt][1]) : "r"(bd));
            }
            #pragma unroll
            for (int mt = 0; mt < 4; mt++)
                #pragma unroll
                for (int nt = 0; nt < 4; nt++)
                    asm volatile("mma.sync.aligned.m16n8k16.row.col.f32.bf16.bf16.f32 "
                        "{%0,%1,%2,%3}, {%4,%5,%6,%7}, {%8,%9}, {%0,%1,%2,%3};"
                        : "+f"(d[mt][nt][0]), "+f"(d[mt][nt][1]),
                          "+f"(d[mt][nt][2]), "+f"(d[mt][nt][3])
                        : "r"(af[mt][0]), "r"(af[mt][1]), "r"(af[mt][2]), "r"(af[mt][3]),
                          "r"(bf_[nt][0]), "r"(bf_[nt][1]));

            // pass 2: Ahi x Blo
            #pragma unroll
            for (int nt = 0; nt < 4; nt++) {
                uint32_t bd = bBL + (uint32_t)(boff + nt * 8 * ROWS) * 2;
                asm volatile("ldmatrix.sync.aligned.m8n8.x2.shared.b16 {%0,%1}, [%2];"
                    : "=r"(bf_[nt][0]), "=r"(bf_[nt][1]) : "r"(bd));
            }
            #pragma unroll
            for (int mt = 0; mt < 4; mt++)
                #pragma unroll
                for (int nt = 0; nt < 4; nt++)
                    asm volatile("mma.sync.aligned.m16n8k16.row.col.f32.bf16.bf16.f32 "
                        "{%0,%1,%2,%3}, {%4,%5,%6,%7}, {%8,%9}, {%0,%1,%2,%3};"
                        : "+f"(d[mt][nt][0]), "+f"(d[mt][nt][1]),
                          "+f"(d[mt][nt][2]), "+f"(d[mt][nt][3])
                        : "r"(af[mt][0]), "r"(af[mt][1]), "r"(af[mt][2]), "r"(af[mt][3]),
                          "r"(bf_[nt][0]), "r"(bf_[nt][1]));

            // pass 3: Alo x Bhi
            #pragma unroll
            for (int mt = 0; mt < 4; mt++) {
                uint32_t ad = bAL + (uint32_t)(aoff + mt * 16 * ROWS) * 2;
                asm volatile("ldmatrix.sync.aligned.m8n8.x4.shared.b16 {%0,%1,%2,%3}, [%4];"
                    : "=r"(af[mt][0]), "=r"(af[mt][1]), "=r"(af[mt][2]), "=r"(af[mt][3])
                    : "r"(ad));
            }
            #pragma unroll
            for (int nt = 0; nt < 4; nt++) {
                uint32_t bd = bBH + (uint32_t)(boff + nt * 8 * ROWS) * 2;
                asm volatile("ldmatrix.sync.aligned.m8n8.x2.shared.b16 {%0,%1}, [%2];"
                    : "=r"(bf_[nt][0]), "=r"(bf_[nt][1]) : "r"(bd));
            }
            #pragma unroll
            for (int mt = 0; mt < 4; mt++)
                #pragma unroll
                for (int nt = 0; nt < 4; nt++)
                    asm volatile("mma.sync.aligned.m16n8k16.row.col.f32.bf16.bf16.f32 "
                        "{%0,%1,%2,%3}, {%4,%5,%6,%7}, {%8,%9}, {%0,%1,%2,%3};"
                        : "+f"(d[mt][nt][0]), "+f"(d[mt][nt][1]),
                          "+f"(d[mt][nt][2]), "+f"(d[mt][nt][3])
                        : "r"(af[mt][0]), "r"(af[mt][1]), "r"(af[mt][2]), "r"(af[mt][3]),
                          "r"(bf_[nt][0]), "r"(bf_[nt][1]));
        }
        __syncthreads();
    }

    // ---------------- epilogue ----------------
    float* outF = g.outF ? g.outF + (long)z * g.cZ : nullptr;
    bf16* oHi = g.oHi ? g.oHi + (long)z * g.cZ : nullptr;
    bf16* oLo = g.oLo ? g.oLo + (long)z * g.cZ : nullptr;
    const float* aux1 = g.aux1 ? g.aux1 + (long)z * g.a1Z : nullptr;
    const int blkN = (EPI == 8) ? col0 / 768 : 0;
    const int cc0  = (EPI == 8) ? col0 - blkN * 768 : col0;
    const int ostride = (EPI == 8) ? 768 : Nn;
    const float* biasp = (EPI == 8) ? (blkN == 0 ? g.bias : (blkN == 1 ? g.bias2 : g.bias3))
                                    : g.bias;

    #pragma unroll
    for (int mt = 0; mt < 4; mt++) {
        int r0 = row0 + wm * 64 + mt * 16 + (lane >> 2);
        int r1 = r0 + 8;
        float dn0 = 1.f, dn1 = 1.f;
        if (EPI == 3) {
            const float* dz = g.den + (long)z * g.denZ;
            dn0 = dz[r0]; dn1 = dz[r1];
        }
        float gv0[8], gv1[8];
        if (EPI == 4 && z == 0) {
            #pragma unroll
            for (int e = 0; e < 8; e++) {
                gv0[e] = __ldg(&g.gate[(long)r0 * 8 + e]);
                gv1[e] = __ldg(&g.gate[(long)r1 * 8 + e]);
            }
        }
        #pragma unroll
        for (int nt = 0; nt < 4; nt++) {
            int c0 = cc0 + wn * 32 + nt * 8 + 2 * (lane & 3);
            #pragma unroll
            for (int half = 0; half < 2; half++) {
                int rg = half ? r1 : r0;
                float dn = half ? dn1 : dn0;
                const float* gv = half ? gv1 : gv0;
                #pragma unroll
                for (int jj = 0; jj < 2; jj++) {
                    int col = c0 + jj;
                    float x = d[mt][nt][half * 2 + jj];
                    long idx = (long)rg * ostride + col;
                    if (EPI == 8) {
                        float t = x + __ldg(&biasp[col]);
                        if (blkN == 0) {
                            float o = (t > 0.f) ? (t + 1.f) : __expf(t);
                            outF[idx] = o;
                            bf16 hi, lo; split2(o, hi, lo);
                            oHi[idx] = hi; oLo[idx] = lo;
                        } else if (blkN == 1) {
                            g.outF2[idx] = (t > 0.f) ? (t + 1.f) : __expf(t);
                        } else {
                            g.outF3[idx] = t;
                        }
                    } else if (EPI == 9) {
                        bf16 hi, lo; split2(x, hi, lo);
                        oHi[idx] = hi; oLo[idx] = lo;
                    } else if (EPI == 10) {
                        float t = x + __ldg(&g.bias[col]);
                        float o = 1.f / (1.f + __expf(-t));
                        bf16 hi, lo; split2(o, hi, lo);
                        oHi[idx] = hi; oLo[idx] = lo;
                    } else if (EPI == 1) {
                        float o = x + (g.bias ? __ldg(&g.bias[col]) : 0.f);
                        outF[idx] = o;
                        if (g.outF2) g.outF2[idx] = o;
                    } else if (EPI == 3) {
                        outF[idx] = x / dn + aux1[idx];
                    } else if (EPI == 4) {
                        float o = x;
                        if (z == 0) {
                            float bm = 0.f;
                            #pragma unroll
                            for (int e = 0; e < 8; e++)
                                bm = fmaf(gv[e], __ldg(&g.ebias[e * Nn + col]), bm);
                            o += bm;
                        }
                        outF[idx] = o;
                    } else if (EPI == 6) {
                        float t = x + __ldg(&g.bias[col]);
                        outF[idx] = 1.f / (1.f + __expf(-t)) + g.aux1[idx] + g.aux2[idx];
                    } else { // 7
                        outF[idx] = x * 2.0f;
                    }
                }
            }
        }
    }
}

// ---------- prepack: dst[n,k] = split(src[k,n]) ----------
__global__ __launch_bounds__(256)
void tsplit(const float* __restrict__ src, bf16* dhi, bf16* dlo, int K, int N,
            int mode, long outZ, long rowOff)
{
    __shared__ float t[32][33];
    int z = blockIdx.z;
    const float* s = src + (long)z * K * N;
    long dbase; int dld;
    if (mode == 1) { int l = z >> 3, e = z & 7; dbase = (long)l * 8 * UU + (long)e * U_DIM; dld = 6144; }
    else { dbase = (long)z * outZ + rowOff; dld = K; }
    int n0 = blockIdx.x * 32, k0 = blockIdx.y * 32;
    int tx = threadIdx.x & 31, ty = threadIdx.x >> 5;
    #pragma unroll
    for (int i = 0; i < 32; i += 8) t[ty + i][tx] = s[(long)(k0 + ty + i) * N + n0 + tx];
    __syncthreads();
    #pragma unroll
    for (int i = 0; i < 32; i += 8) {
        float v = t[tx][ty + i];
        bf16 hi, lo; split2(v, hi, lo);
        long di = dbase + (long)(n0 + ty + i) * dld + k0 + tx;
        dhi[di] = hi; dlo[di] = lo;
    }
}

// ---------- small kernels ----------
__device__ __forceinline__ float warpSum(float v) {
    #pragma unroll
    for (int o = 16; o > 0; o >>= 1) v += __shfl_xor_sync(0xffffffffu, v, o);
    return v;
}
__global__ __launch_bounds__(192)
void gather_split(const int* __restrict__ x, const float* __restrict__ emb, bf16* xhi, bf16* xlo)
{
    int row = blockIdx.x, tok = x[row];
    const float* s = emb + (long)tok * U_DIM;
    for (int i = threadIdx.x; i < U_DIM; i += 192) {
        bf16 hi, lo; split2(s[i], hi, lo);
        xhi[(long)row * U_DIM + i] = hi; xlo[(long)row * U_DIM + i] = lo;
    }
}
__global__ __launch_bounds__(256)
void rms_split(const float* __restrict__ h, float* n, bf16* nhi, bf16* nlo)
{
    long row = blockIdx.x;
    const float* hr = h + row * U_DIM;
    float s = 0.f;
    for (int u = threadIdx.x; u < U_DIM; u += 256) { float t = hr[u]; s = fmaf(t, t, s); }
    s = warpSum(s);
    __shared__ float red[8]; __shared__ float rsh;
    int wid = threadIdx.x >> 5, lane = threadIdx.x & 31;
    if (lane == 0) red[wid] = s;
    __syncthreads();
    if (threadIdx.x == 0) {
        float tot = 0.f;
        #pragma unroll
        for (int i = 0; i < 8; i++) tot += red[i];
        rsh = rsqrtf(tot / (float)U_DIM + EPS_F);
    }
    __syncthreads();
    float r = rsh;
    for (int u = threadIdx.x; u < U_DIM; u += 256) {
        float o = hr[u] * r;
        if (n) n[row * U_DIM + u] = o;
        bf16 hi, lo; split2(o, hi, lo);
        nhi[row * U_DIM + u] = hi; nlo[row * U_DIM + u] = lo;
    }
}
__global__ __launch_bounds__(256)
void gatemul(const float* __restrict__ n, const float* __restrict__ gate, bf16* hi, bf16* lo)
{
    long i = (long)blockIdx.x * 256 + threadIdx.x;   // BT*6144
    int t = (int)(i / 6144), r = (int)(i % 6144);
    int e = r / 768, u = r % 768;
    float v = gate[(long)t * 8 + e] * n[(long)t * 768 + u];
    bf16 h, l; split2(v, h, l); hi[i] = h; lo[i] = l;
}
__global__ __launch_bounds__(256)
void colsum(const float* __restrict__ kb, float* ks)
{
    int b = blockIdx.y;
    int u = blockIdx.x * 256 + threadIdx.x;
    const float* p = kb + (long)b * T_DIM * U_DIM;
    float s = 0.f;
    for (int t = 0; t < T_DIM; t++) s += p[(long)t * U_DIM + u];
    ks[b * U_DIM + u] = s;
}
__global__ __launch_bounds__(256)
void denk(const float* __restrict__ q, const float* __restrict__ ks, float* den)
{
    int gw = (blockIdx.x * 256 + threadIdx.x) >> 5;
    int lane = threadIdx.x & 31;
    if (gw >= BT) return;
    int b = gw >> 10;
    const float* qr = q + (long)gw * U_DIM;
    const float* kb = ks + b * U_DIM;
    float s = 0.f;
    for (int u = lane; u < U_DIM; u += 32) s = fmaf(qr[u], kb[u], s);
    s = warpSum(s);
    if (lane == 0) den[gw] = s + EPS_F;
}
__global__ __launch_bounds__(256)
void gatek(const float* __restrict__ n, const float* __restrict__ gWl,
           const float* __restrict__ gbl, float* gate)
{
    int row = blockIdx.x;
    int wid = threadIdx.x >> 5, lane = threadIdx.x & 31;
    const float* nr = n + (long)row * U_DIM;
    float s = 0.f;
    for (int u = lane; u < U_DIM; u += 32) s = fmaf(nr[u], gWl[u * E_DIM + wid], s);
    s = warpSum(s);
    __shared__ float sl[E_DIM];
    if (lane == 0) sl[wid] = s + gbl[wid];
    __syncthreads();
    if (threadIdx.x == 0) {
        float mx = sl[0];
        #pragma unroll
        for (int e = 1; e < E_DIM; e++) mx = fmaxf(mx, sl[e]);
        float ex[E_DIM], sum = 0.f;
        #pragma unroll
        for (int e = 0; e < E_DIM; e++) { ex[e] = __expf(sl[e] - mx); sum += ex[e]; }
        float inv = 1.f / sum;
        #pragma unroll
        for (int e = 0; e < E_DIM; e++) gate[(long)row * E_DIM + e] = ex[e] * inv;
    }
}
__global__ __launch_bounds__(256)
void addk(const float* __restrict__ a, const float* __restrict__ b, float* c, int n)
{
    int i = blockIdx.x * 256 + threadIdx.x;
    if (i < n) c[i] = a[i] + b[i];
}

// ---------- host dispatch ----------
static void tc(int epi, GArgs& a, int M, int N, int Z)
{
    dim3 g(N / 128, M / 128, Z);
    switch (epi) {
    case 1:  mma_gemm<1><<<g, 256, DSM>>>(a); break;
    case 3:  mma_gemm<3><<<g, 256, DSM>>>(a); break;
    case 4:  mma_gemm<4><<<g, 256, DSM>>>(a); break;
    case 6:  mma_gemm<6><<<g, 256, DSM>>>(a); break;
    case 7:  mma_gemm<7><<<g, 256, DSM>>>(a); break;
    case 8:  mma_gemm<8><<<g, 256, DSM>>>(a); break;
    case 9:  mma_gemm<9><<<g, 256, DSM>>>(a); break;
    case 10: mma_gemm<10><<<g, 256, DSM>>>(a); break;
    }
}

extern "C" void kernel_launch(void* const* d_in, const int* in_sizes, int n_in,
                              void* d_out, int out_size)
{
    const int*   x    = (const int*)  d_in[0];
    const float* emb  = (const float*)d_in[1];
    const float* W_in = (const float*)d_in[2];
    const float* Wq   = (const float*)d_in[3];
    const float* bq   = (const float*)d_in[4];
    const float* Wk   = (const float*)d_in[5];
    const float* bk   = (const float*)d_in[6];
    const float* Wv   = (const float*)d_in[7];
    const float* bv   = (const float*)d_in[8];
    const float* gW   = (const float*)d_in[9];
    const float* gb   = (const float*)d_in[10];
    const float* eW   = (const float*)d_in[11];
    const float* eb   = (const float*)d_in[12];
    const float* fW1  = (const float*)d_in[13];
    const float* fb1  = (const float*)d_in[14];
    const float* fW2  = (const float*)d_in[15];
    const float* fb2  = (const float*)d_in[16];
    const float* Wlog = (const float*)d_in[17];
    float* out = (float*)d_out;

    cudaFuncSetAttribute(mma_gemm<1>,  cudaFuncAttributeMaxDynamicSharedMemorySize, DSM);
    cudaFuncSetAttribute(mma_gemm<3>,  cudaFuncAttributeMaxDynamicSharedMemorySize, DSM);
    cudaFuncSetAttribute(mma_gemm<4>,  cudaFuncAttributeMaxDynamicSharedMemorySize, DSM);
    cudaFuncSetAttribute(mma_gemm<6>,  cudaFuncAttributeMaxDynamicSharedMemorySize, DSM);
    cudaFuncSetAttribute(mma_gemm<7>,  cudaFuncAttributeMaxDynamicSharedMemorySize, DSM);
    cudaFuncSetAttribute(mma_gemm<8>,  cudaFuncAttributeMaxDynamicSharedMemorySize, DSM);
    cudaFuncSetAttribute(mma_gemm<9>,  cudaFuncAttributeMaxDynamicSharedMemorySize, DSM);
    cudaFuncSetAttribute(mma_gemm<10>, cudaFuncAttributeMaxDynamicSharedMemorySize, DSM);

    bf16 *whi, *wlo;
    float *h, *h0, *hA, *hM, *n, *q, *k, *v, *mo, *ksum, *den, *gate;
    bf16 *nhi, *nlo, *xhi, *xlo, *qhi, *qlo, *kthi, *ktlo, *vthi, *vtlo;
    bf16 *kvhi, *kvlo, *f1hi, *f1lo, *amhi, *amlo;
    cudaGetSymbolAddress((void**)&whi, g_whi);  cudaGetSymbolAddress((void**)&wlo, g_wlo);
    cudaGetSymbolAddress((void**)&h, g_h);      cudaGetSymbolAddress((void**)&h0, g_h0);
    cudaGetSymbolAddress((void**)&hA, g_hA);    cudaGetSymbolAddress((void**)&hM, g_hM);
    cudaGetSymbolAddress((void**)&n, g_n);
    cudaGetSymbolAddress((void**)&q, g_q);      cudaGetSymbolAddress((void**)&k, g_k);
    cudaGetSymbolAddress((void**)&v, g_v);      cudaGetSymbolAddress((void**)&mo, g_mo);
    cudaGetSymbolAddress((void**)&ksum, g_ksum);
    cudaGetSymbolAddress((void**)&den, g_den);  cudaGetSymbolAddress((void**)&gate, g_gate);
    cudaGetSymbolAddress((void**)&nhi, g_nhi);  cudaGetSymbolAddress((void**)&nlo, g_nlo);
    cudaGetSymbolAddress((void**)&xhi, g_xhi);  cudaGetSymbolAddress((void**)&xlo, g_xlo);
    cudaGetSymbolAddress((void**)&qhi, g_qhi);  cudaGetSymbolAddress((void**)&qlo, g_qlo);
    cudaGetSymbolAddress((void**)&kthi, g_kthi); cudaGetSymbolAddress((void**)&ktlo, g_ktlo);
    cudaGetSymbolAddress((void**)&vthi, g_vthi); cudaGetSymbolAddress((void**)&vtlo, g_vtlo);
    cudaGetSymbolAddress((void**)&kvhi, g_kvhi); cudaGetSymbolAddress((void**)&kvlo, g_kvlo);
    cudaGetSymbolAddress((void**)&f1hi, g_f1hi); cudaGetSymbolAddress((void**)&f1lo, g_f1lo);
    cudaGetSymbolAddress((void**)&amhi, g_amhi); cudaGetSymbolAddress((void**)&amlo, g_amlo);

    const long TU = (long)T_DIM * U_DIM;
    const long HN = (long)BT * U_DIM;

    // ---- weight prepack: transpose+split into arena ----
    tsplit<<<dim3(24, 24, 1),   256>>>(W_in, whi + OFF_WIN, wlo + OFF_WIN, 768, 768, 0, UU, 0);
    tsplit<<<dim3(24, 24, 16),  256>>>(Wq, whi + OFF_QKV, wlo + OFF_QKV, 768, 768, 0, 3 * UU, 0);
    tsplit<<<dim3(24, 24, 16),  256>>>(Wk, whi + OFF_QKV, wlo + OFF_QKV, 768, 768, 0, 3 * UU, UU);
    tsplit<<<dim3(24, 24, 16),  256>>>(Wv, whi + OFF_QKV, wlo + OFF_QKV, 768, 768, 0, 3 * UU, 2 * UU);
    tsplit<<<dim3(24, 24, 16),  256>>>(fW1, whi + OFF_F1, wlo + OFF_F1, 768, 768, 0, UU, 0);
    tsplit<<<dim3(24, 24, 16),  256>>>(fW2, whi + OFF_F2, wlo + OFF_F2, 768, 768, 0, UU, 0);
    tsplit<<<dim3(24, 24, 128), 256>>>(eW, whi + OFF_EW, wlo + OFF_EW, 768, 768, 1, 0, 0);
    tsplit<<<dim3(1000, 24, 1), 256>>>(Wlog, whi + OFF_WLOG, wlo + OFF_WLOG, 768, 32000, 0, 0, 0);

    GArgs a;

    // ---- h0 = emb[x] @ W_in ; h = h0 ----
    gather_split<<<BT, 192>>>(x, emb, xhi, xlo);
    a = {}; a.Ahi = xhi; a.Alo = xlo; a.Bhi = whi + OFF_WIN; a.Blo = wlo + OFF_WIN;
    a.N = 768; a.K = 768; a.outF = h0; a.outF2 = h;
    tc(1, a, BT, 768, 1);

    for (int l = 0; l < L_DIM; l++) {
        // --- linear attention: inp = h (kept), result -> hA ---
        rms_split<<<BT, 256>>>(h, n, nhi, nlo);
        a = {}; a.Ahi = nhi; a.Alo = nlo;
        a.Bhi = whi + OFF_QKV + (long)l * 3 * UU; a.Blo = wlo + OFF_QKV + (long)l * 3 * UU;
        a.N = 768; a.K = 768;
        a.bias = bq + l * U_DIM; a.bias2 = bk + l * U_DIM; a.bias3 = bv + l * U_DIM;
        a.outF = q; a.outF2 = k; a.outF3 = v; a.oHi = qhi; a.oLo = qlo;
        tc(8, a, BT, 2304, 1);
        tsplit<<<dim3(24, 32, 2), 256>>>(k, kthi, ktlo, 1024, 768, 0, TU, 0);
        tsplit<<<dim3(24, 32, 2), 256>>>(v, vthi, vtlo, 1024, 768, 0, TU, 0);
        // kvT[b][v][u] = sum_t v[t,v]*k[t,u]  -> split write
        a = {}; a.Ahi = vthi; a.Alo = vtlo; a.Bhi = kthi; a.Blo = ktlo;
        a.N = 768; a.K = 1024; a.aZ = TU; a.bZ = TU; a.cZ = UU;
        a.oHi = kvhi; a.oLo = kvlo;
        tc(9, a, 768, 768, 2);
        colsum<<<dim3(3, 2), 256>>>(k, ksum);
        denk<<<256, 256>>>(q, ksum, den);
        // hA = (q @ kv) / den + h
        a = {}; a.Ahi = qhi; a.Alo = qlo; a.Bhi = kvhi; a.Blo = kvlo;
        a.N = 768; a.K = 768; a.aZ = TU; a.bZ = UU; a.cZ = TU;
        a.den = den; a.denZ = T_DIM; a.aux1 = h; a.a1Z = TU; a.outF = hA;
        tc(3, a, T_DIM, 768, 2);

        // --- soft MoE: hM = moe(rms(hA)) ---
        rms_split<<<BT, 256>>>(hA, n, nhi, nlo);
        gatek<<<BT, 256>>>(n, gW + (long)l * U_DIM * E_DIM, gb + l * E_DIM, gate);
        gatemul<<<(BT * 6144) / 256, 256>>>(n, gate, amhi, amlo);
        a = {}; a.Ahi = amhi; a.Alo = amlo;
        a.Bhi = whi + OFF_EW + (long)l * 8 * UU; a.Blo = wlo + OFF_EW + (long)l * 8 * UU;
        a.N = 768; a.K = 6144; a.kSplit = 3072; a.cZ = HN;
        a.gate = gate; a.ebias = eb + (long)l * E_DIM * U_DIM; a.outF = mo;
        tc(4, a, BT, 768, 2);
        addk<<<(BT * U_DIM) / 256, 256>>>(mo, mo + HN, hM, BT * U_DIM);

        // --- FFN: h = sigmoid(sigmoid(rms(hM)@f1+b1)@f2+b2) + hM + h ---
        rms_split<<<BT, 256>>>(hM, n, nhi, nlo);
        a = {}; a.Ahi = nhi; a.Alo = nlo;
        a.Bhi = whi + OFF_F1 + (long)l * UU; a.Blo = wlo + OFF_F1 + (long)l * UU;
        a.N = 768; a.K = 768; a.bias = fb1 + l * U_DIM; a.oHi = f1hi; a.oLo = f1lo;
        tc(10, a, BT, 768, 1);
        a = {}; a.Ahi = f1hi; a.Alo = f1lo;
        a.Bhi = whi + OFF_F2 + (long)l * UU; a.Blo = wlo + OFF_F2 + (long)l * UU;
        a.N = 768; a.K = 768; a.bias = fb2 + l * U_DIM;
        a.aux1 = hM; a.aux2 = h; a.outF = h;
        tc(6, a, BT, 768, 1);
    }

    // ---- final norms + logits ----
    rms_split<<<BT, 256>>>(h, n, nhi, nlo);
    addk<<<(BT * U_DIM) / 256, 256>>>(n, h0, hA, BT * U_DIM);
    rms_split<<<BT, 256>>>(hA, nullptr, nhi, nlo);
    a = {}; a.Ahi = nhi; a.Alo = nlo;
    a.Bhi = whi + OFF_WLOG; a.Blo = wlo + OFF_WLOG;
    a.N = 32000; a.K = 768; a.outF = out;
    tc(7, a, BT, 32000, 1);
}

// round 8
// speedup vs baseline: 2.7174x; 1.3828x over previous
#include <cuda_runtime.h>
#include <cuda_bf16.h>
#include <cstdint>

#define U_DIM 768
#define T_DIM 1024
#define B_DIM 2
#define BT    2048
#define E_DIM 8
#define L_DIM 16
#define V_DIM 32000
#define EPS_F 1e-6f
#define UU    589824L
#define TU    786432L          // T*U
#define HN    1572864L         // BT*U

#define OFF_WIN  0L
#define OFF_QKV  (UU)
#define OFF_F1   (OFF_QKV + 48L*UU)
#define OFF_F2   (OFF_F1 + 16L*UU)
#define OFF_EW   (OFF_F2 + 16L*UU)
#define OFF_WLOG (OFF_EW + 128L*UU)
#define W_TOTAL  (OFF_WLOG + 32000L*768L)

typedef __nv_bfloat16 bf16;

__device__ bf16 g_whi[W_TOTAL];
__device__ bf16 g_wlo[W_TOTAL];
__device__ float g_h[HN], g_h0[HN], g_hA[HN], g_hM[HN], g_n[HN];
__device__ float g_mo[3*HN];
__device__ float g_ksum[B_DIM*U_DIM], g_den[BT], g_gate[BT*E_DIM];
__device__ bf16 g_nhi[HN],  g_nlo[HN];
__device__ bf16 g_xhi[HN],  g_xlo[HN];
__device__ bf16 g_qhi[HN],  g_qlo[HN];
__device__ bf16 g_kthi[HN], g_ktlo[HN];   // [B][U][T]
__device__ bf16 g_vthi[HN], g_vtlo[HN];   // [B][U][T]
__device__ bf16 g_kvhi[B_DIM*UU], g_kvlo[B_DIM*UU];
__device__ bf16 g_f1hi[HN], g_f1lo[HN];
__device__ bf16 g_amhi[BT*6144L], g_amlo[BT*6144L];

__device__ __forceinline__ uint32_t smem_u32(const void* p) {
    uint32_t a;
    asm("{ .reg .u64 t; cvta.to.shared.u64 t, %1; cvt.u32.u64 %0, t; }" : "=r"(a) : "l"(p));
    return a;
}
__device__ __forceinline__ void split2(float x, bf16& hi, bf16& lo) {
    hi = __float2bfloat16(x);
    lo = __float2bfloat16(x - __bfloat162float(hi));
}
__device__ __forceinline__ float warpSum(float v) {
    #pragma unroll
    for (int o = 16; o > 0; o >>= 1) v += __shfl_xor_sync(0xffffffffu, v, o);
    return v;
}

struct GArgs {
    const bf16 *Ahi, *Alo, *Bhi, *Blo;
    int N, K, kSplit, SK;
    long aZ, bZ, cZ;
    const float *bias, *bias2, *bias3;
    float *outF, *outF2;
    bf16 *oHi, *oLo, *oHi2, *oLo2, *oHi3, *oLo3;
};

#define ROWS 72
#define TB   (128 * ROWS * 2)
#define DSM  (8 * TB)          // 147456

// EPI: 1 out(+copy), 2 partial, 7 x2, 8 qkv(q-split / kT / vT)
template<int EPI>
__global__ __launch_bounds__(256)
void mma_gemm(GArgs g)
{
    extern __shared__ char smem[];
    uint32_t sb = smem_u32(smem);
    const int tid = threadIdx.x, wid = tid >> 5, lane = tid & 31;
    const int wm = wid >> 2, wn = wid & 3;
    const int z = blockIdx.z;
    const int zB = g.SK > 1 ? z / g.SK : z;
    const int zS = g.SK > 1 ? z % g.SK : 0;
    const int row0 = blockIdx.y * 128, col0 = blockIdx.x * 128;
    const int Nn = g.N, K = g.K;

    const bf16* Ahi = g.Ahi + (long)zB * g.aZ;
    const bf16* Alo = g.Alo + (long)zB * g.aZ;
    const bf16* Bhi = g.Bhi + (long)zB * g.bZ;
    const bf16* Blo = g.Blo + (long)zB * g.bZ;
    const int kbase = g.kSplit ? zS * g.kSplit : 0;
    const int CH = (g.kSplit ? g.kSplit : K) >> 6;

    float d[4][4][4];
    #pragma unroll
    for (int a = 0; a < 4; a++)
        #pragma unroll
        for (int b = 0; b < 4; b++)
            #pragma unroll
            for (int c = 0; c < 4; c++) d[a][b][c] = 0.f;

    auto issue = [&](int c, int s) {
        int k0 = kbase + (c << 6);
        const bf16* srcs[4] = {
            Ahi + (long)row0 * K + k0, Alo + (long)row0 * K + k0,
            Bhi + (long)col0 * K + k0, Blo + (long)col0 * K + k0 };
        #pragma unroll
        for (int t = 0; t < 4; t++) {
            uint32_t dst = sb + (uint32_t)(s * 4 + t) * TB;
            #pragma unroll
            for (int i = 0; i < 4; i++) {
                int idx = tid + (i << 8);
                int r = idx >> 3, cc = idx & 7;
                uint32_t doff = (uint32_t)(r * ROWS + cc * 8) * 2;
                const void* sp = srcs[t] + (long)r * K + cc * 8;
                asm volatile("cp.async.cg.shared.global [%0], [%1], 16;"
                             :: "r"(dst + doff), "l"(sp));
            }
        }
        asm volatile("cp.async.commit_group;");
    };

    issue(0, 0);
    for (int c = 0; c < CH; c++) {
        int s = c & 1;
        if (c + 1 < CH) { issue(c + 1, s ^ 1); asm volatile("cp.async.wait_group 1;"); }
        else            { asm volatile("cp.async.wait_group 0;"); }
        __syncthreads();
        uint32_t bAH = sb + (uint32_t)(s * 4 + 0) * TB;
        uint32_t bAL = sb + (uint32_t)(s * 4 + 1) * TB;
        uint32_t bBH = sb + (uint32_t)(s * 4 + 2) * TB;
        uint32_t bBL = sb + (uint32_t)(s * 4 + 3) * TB;
        #pragma unroll
        for (int ks = 0; ks < 4; ks++) {
            int k16 = ks * 16;
            int aoff = (wm * 64 + (lane & 15)) * ROWS + k16 + ((lane >> 4) << 3);
            int boff = (wn * 32 + (lane & 7)) * ROWS + k16 + (((lane >> 3) & 1) << 3);
            uint32_t af[4][4], bf_[4][2];
            #pragma unroll
            for (int mt = 0; mt < 4; mt++) {
                uint32_t ad = bAH + (uint32_t)(aoff + mt * 16 * ROWS) * 2;
                asm volatile("ldmatrix.sync.aligned.m8n8.x4.shared.b16 {%0,%1,%2,%3}, [%4];"
                    : "=r"(af[mt][0]), "=r"(af[mt][1]), "=r"(af[mt][2]), "=r"(af[mt][3]) : "r"(ad));
            }
            #pragma unroll
            for (int nt = 0; nt < 4; nt++) {
                uint32_t bd = bBH + (uint32_t)(boff + nt * 8 * ROWS) * 2;
                asm volatile("ldmatrix.sync.aligned.m8n8.x2.shared.b16 {%0,%1}, [%2];"
                    : "=r"(bf_[nt][0]), "=r"(bf_[nt][1]) : "r"(bd));
            }
            #pragma unroll
            for (int mt = 0; mt < 4; mt++)
                #pragma unroll
                for (int nt = 0; nt < 4; nt++)
                    asm volatile("mma.sync.aligned.m16n8k16.row.col.f32.bf16.bf16.f32 "
                        "{%0,%1,%2,%3}, {%4,%5,%6,%7}, {%8,%9}, {%0,%1,%2,%3};"
                        : "+f"(d[mt][nt][0]), "+f"(d[mt][nt][1]), "+f"(d[mt][nt][2]), "+f"(d[mt][nt][3])
                        : "r"(af[mt][0]), "r"(af[mt][1]), "r"(af[mt][2]), "r"(af[mt][3]),
                          "r"(bf_[nt][0]), "r"(bf_[nt][1]));
            #pragma unroll
            for (int nt = 0; nt < 4; nt++) {
                uint32_t bd = bBL + (uint32_t)(boff + nt * 8 * ROWS) * 2;
                asm volatile("ldmatrix.sync.aligned.m8n8.x2.shared.b16 {%0,%1}, [%2];"
                    : "=r"(bf_[nt][0]), "=r"(bf_[nt][1]) : "r"(bd));
            }
            #pragma unroll
            for (int mt = 0; mt < 4; mt++)
                #pragma unroll
                for (int nt = 0; nt < 4; nt++)
                    asm volatile("mma.sync.aligned.m16n8k16.row.col.f32.bf16.bf16.f32 "
                        "{%0,%1,%2,%3}, {%4,%5,%6,%7}, {%8,%9}, {%0,%1,%2,%3};"
                        : "+f"(d[mt][nt][0]), "+f"(d[mt][nt][1]), "+f"(d[mt][nt][2]), "+f"(d[mt][nt][3])
                        : "r"(af[mt][0]), "r"(af[mt][1]), "r"(af[mt][2]), "r"(af[mt][3]),
                          "r"(bf_[nt][0]), "r"(bf_[nt][1]));
            #pragma unroll
            for (int mt = 0; mt < 4; mt++) {
                uint32_t ad = bAL + (uint32_t)(aoff + mt * 16 * ROWS) * 2;
                asm volatile("ldmatrix.sync.aligned.m8n8.x4.shared.b16 {%0,%1,%2,%3}, [%4];"
                    : "=r"(af[mt][0]), "=r"(af[mt][1]), "=r"(af[mt][2]), "=r"(af[mt][3]) : "r"(ad));
            }
            #pragma unroll
            for (int nt = 0; nt < 4; nt++) {
                uint32_t bd = bBH + (uint32_t)(boff + nt * 8 * ROWS) * 2;
                asm volatile("ldmatrix.sync.aligned.m8n8.x2.shared.b16 {%0,%1}, [%2];"
                    : "=r"(bf_[nt][0]), "=r"(bf_[nt][1]) : "r"(bd));
            }
            #pragma unroll
            for (int mt = 0; mt < 4; mt++)
                #pragma unroll
                for (int nt = 0; nt < 4; nt++)
                    asm volatile("mma.sync.aligned.m16n8k16.row.col.f32.bf16.bf16.f32 "
                        "{%0,%1,%2,%3}, {%4,%5,%6,%7}, {%8,%9}, {%0,%1,%2,%3};"
                        : "+f"(d[mt][nt][0]), "+f"(d[mt][nt][1]), "+f"(d[mt][nt][2]), "+f"(d[mt][nt][3])
                        : "r"(af[mt][0]), "r"(af[mt][1]), "r"(af[mt][2]), "r"(af[mt][3]),
                          "r"(bf_[nt][0]), "r"(bf_[nt][1]));
        }
        __syncthreads();
    }

    // ---------------- epilogues ----------------
    if (EPI == 8) {
        const int blkN = col0 / 768;
        const int cc0  = col0 - blkN * 768;
        if (blkN == 0) {           // q: phi -> split, row-major
            #pragma unroll
            for (int mt = 0; mt < 4; mt++) {
                #pragma unroll
                for (int half = 0; half < 2; half++) {
                    int rg = row0 + wm * 64 + mt * 16 + (lane >> 2) + half * 8;
                    #pragma unroll
                    for (int nt = 0; nt < 4; nt++) {
                        int col = cc0 + wn * 32 + nt * 8 + 2 * (lane & 3);
                        float t0 = d[mt][nt][half*2+0] + __ldg(&g.bias[col]);
                        float t1 = d[mt][nt][half*2+1] + __ldg(&g.bias[col+1]);
                        float o0 = (t0 > 0.f) ? (t0 + 1.f) : __expf(t0);
                        float o1 = (t1 > 0.f) ? (t1 + 1.f) : __expf(t1);
                        bf16 h0b,l0b,h1b,l1b; split2(o0,h0b,l0b); split2(o1,h1b,l1b);
                        __nv_bfloat162 ph; ph.x=h0b; ph.y=h1b;
                        __nv_bfloat162 pl; pl.x=l0b; pl.y=l1b;
                        long idx = (long)rg * 768 + col;
                        *(__nv_bfloat162*)(g.oHi + idx) = ph;
                        *(__nv_bfloat162*)(g.oLo + idx) = pl;
                    }
                }
            }
        } else {                   // k or v: act -> smem transpose -> split [B][U][T]
            const float* bp = (blkN == 1) ? g.bias2 : g.bias3;
            float* tile = (float*)smem;      // [128][130]
            #pragma unroll
            for (int mt = 0; mt < 4; mt++)
                #pragma unroll
                for (int nt = 0; nt < 4; nt++)
                    #pragma unroll
                    for (int half = 0; half < 2; half++)
                        #pragma unroll
                        for (int jj = 0; jj < 2; jj++) {
                            int r = wm*64 + mt*16 + (lane>>2) + half*8;
                            int cl = wn*32 + nt*8 + 2*(lane&3) + jj;
                            float t = d[mt][nt][half*2+jj] + __ldg(&bp[cc0 + cl]);
                            if (blkN == 1) t = (t > 0.f) ? (t + 1.f) : __expf(t);
                            tile[r * 130 + cl] = t;
                        }
            __syncthreads();
            bf16* dh = (blkN == 1) ? g.oHi2 : g.oHi3;
            bf16* dl = (blkN == 1) ? g.oLo2 : g.oLo3;
            int u_l = tid & 127, th = tid >> 7;
            int bb = row0 >> 10, t0 = row0 & 1023;
            long rowbase = ((long)(bb * 768 + cc0 + u_l)) * 1024 + t0 + th * 64;
            uint32_t hb[32], lb[32];
            #pragma unroll
            for (int j = 0; j < 64; j += 2) {
                float v0 = tile[(th*64 + j) * 130 + u_l];
                float v1 = tile[(th*64 + j + 1) * 130 + u_l];
                bf16 h0b,l0b,h1b,l1b; split2(v0,h0b,l0b); split2(v1,h1b,l1b);
                __nv_bfloat162 ph; ph.x=h0b; ph.y=h1b;
                __nv_bfloat162 pl; pl.x=l0b; pl.y=l1b;
                hb[j>>1] = *(uint32_t*)&ph; lb[j>>1] = *(uint32_t*)&pl;
            }
            uint4* dh4 = (uint4*)(dh + rowbase);
            uint4* dl4 = (uint4*)(dl + rowbase);
            #pragma unroll
            for (int i = 0; i < 8; i++) { dh4[i] = ((uint4*)hb)[i]; dl4[i] = ((uint4*)lb)[i]; }
        }
        return;
    }

    float* outF = g.outF + (long)z * g.cZ;
    #pragma unroll
    for (int mt = 0; mt < 4; mt++)
        #pragma unroll
        for (int half = 0; half < 2; half++) {
            int rg = row0 + wm * 64 + mt * 16 + (lane >> 2) + half * 8;
            #pragma unroll
            for (int nt = 0; nt < 4; nt++) {
                int col = col0 + wn * 32 + nt * 8 + 2 * (lane & 3);
                #pragma unroll
                for (int jj = 0; jj < 2; jj++) {
                    float x = d[mt][nt][half*2+jj];
                    long idx = (long)rg * Nn + col + jj;
                    if (EPI == 2) outF[idx] = x;
                    else if (EPI == 7) outF[idx] = x * 2.0f;
                    else { outF[idx] = x; if (g.outF2) g.outF2[idx] = x; }
                }
            }
        }
}

// ---------- combine kernels: sum ns split partials + epilogue ----------
// MODE 0 attn, 1 f1-sig-split, 2 moe+ebias, 3 f2-sig+2res, 4 plain-split
template<int MODE>
__global__ __launch_bounds__(256)
void comb(const float* __restrict__ p, long segZ, int ns, long total,
          const float* __restrict__ bias, const float* __restrict__ den,
          const float* __restrict__ aux1, const float* __restrict__ aux2,
          const float* __restrict__ gate, const float* __restrict__ eb,
          float* outF, bf16* oHi, bf16* oLo)
{
    long i4 = ((long)blockIdx.x * 256 + threadIdx.x) * 4;
    if (i4 >= total) return;
    long base = (i4 / segZ) * (long)ns * segZ + (i4 % segZ);
    float4 s = *(const float4*)(p + base);
    float4 s1 = *(const float4*)(p + base + segZ);
    s.x += s1.x; s.y += s1.y; s.z += s1.z; s.w += s1.w;
    if (ns == 3) {
        float4 s2 = *(const float4*)(p + base + 2 * segZ);
        s.x += s2.x; s.y += s2.y; s.z += s2.z; s.w += s2.w;
    }
    float v[4] = {s.x, s.y, s.z, s.w};
    int row = (int)(i4 / 768);
    int col = (int)(i4 % 768);
    if (MODE == 0) {
        float dn = den[row];
        float4 a = *(const float4*)(aux1 + i4);
        float o[4] = {v[0]/dn + a.x, v[1]/dn + a.y, v[2]/dn + a.z, v[3]/dn + a.w};
        *(float4*)(outF + i4) = *(float4*)o;
    } else if (MODE == 2) {
        float gv[8];
        #pragma unroll
        for (int e = 0; e < 8; e++) gv[e] = gate[(long)row * 8 + e];
        #pragma unroll
        for (int j = 0; j < 4; j++) {
            float bm = 0.f;
            #pragma unroll
            for (int e = 0; e < 8; e++) bm = fmaf(gv[e], __ldg(&eb[e * 768 + col + j]), bm);
            v[j] += bm;
        }
        *(float4*)(outF + i4) = *(float4*)v;
    } else if (MODE == 3) {
        float4 a = *(const float4*)(aux1 + i4);
        float4 b2 = *(const float4*)(aux2 + i4);
        float av[4] = {a.x,a.y,a.z,a.w}, bv2[4] = {b2.x,b2.y,b2.z,b2.w};
        float o[4];
        #pragma unroll
        for (int j = 0; j < 4; j++) {
            float t = v[j] + __ldg(&bias[col + j]);
            o[j] = 1.f / (1.f + __expf(-t)) + av[j] + bv2[j];
        }
        *(float4*)(outF + i4) = *(float4*)o;
    } else {
        bf16 hh[4], ll[4];
        #pragma unroll
        for (int j = 0; j < 4; j++) {
            float o = v[j];
            if (MODE == 1) { float t = o + __ldg(&bias[col + j]); o = 1.f / (1.f + __expf(-t)); }
            split2(o, hh[j], ll[j]);
        }
        *(uint2*)(oHi + i4) = *(uint2*)hh;
        *(uint2*)(oLo + i4) = *(uint2*)ll;
    }
}

// ---------- prepack ----------
__global__ __launch_bounds__(256)
void tsplit(const float* __restrict__ src, bf16* dhi, bf16* dlo, int K, int N,
            int mode, long outZ, long rowOff)
{
    __shared__ float t[32][33];
    int z = blockIdx.z;
    const float* s = src + (long)z * K * N;
    long dbase; int dld;
    if (mode == 1) { int l = z >> 3, e = z & 7; dbase = (long)l * 8 * UU + (long)e * U_DIM; dld = 6144; }
    else { dbase = (long)z * outZ + rowOff; dld = K; }
    int n0 = blockIdx.x * 32, k0 = blockIdx.y * 32;
    int tx = threadIdx.x & 31, ty = threadIdx.x >> 5;
    #pragma unroll
    for (int i = 0; i < 32; i += 8) t[ty + i][tx] = s[(long)(k0 + ty + i) * N + n0 + tx];
    __syncthreads();
    #pragma unroll
    for (int i = 0; i < 32; i += 8) {
        float v = t[tx][ty + i];
        bf16 hi, lo; split2(v, hi, lo);
        long di = dbase + (long)(n0 + ty + i) * dld + k0 + tx;
        dhi[di] = hi; dlo[di] = lo;
    }
}

// ---------- small kernels ----------
__global__ __launch_bounds__(192)
void gather_split(const int* __restrict__ x, const float* __restrict__ emb, bf16* xhi, bf16* xlo)
{
    int row = blockIdx.x, tok = x[row];
    const float* s = emb + (long)tok * U_DIM;
    for (int i = threadIdx.x; i < U_DIM; i += 192) {
        bf16 hi, lo; split2(s[i], hi, lo);
        xhi[(long)row * U_DIM + i] = hi; xlo[(long)row * U_DIM + i] = lo;
    }
}

// rms + split; GATE: also softmax(n@gW+gb); WN: write n fp32
template<int GATE, int WN>
__global__ __launch_bounds__(256)
void rms_split(const float* __restrict__ h, float* n, bf16* nhi, bf16* nlo,
               const float* __restrict__ gWl, const float* __restrict__ gbl, float* gate)
{
    long row = blockIdx.x;
    const float* hr = h + row * U_DIM;
    float s = 0.f;
    for (int u = threadIdx.x; u < U_DIM; u += 256) { float t = hr[u]; s = fmaf(t, t, s); }
    s = warpSum(s);
    __shared__ float red[8]; __shared__ float rsh; __shared__ float gsl[8][8];
    int wid = threadIdx.x >> 5, lane = threadIdx.x & 31;
    if (lane == 0) red[wid] = s;
    __syncthreads();
    if (threadIdx.x == 0) {
        float tot = 0.f;
        #pragma unroll
        for (int i = 0; i < 8; i++) tot += red[i];
        rsh = rsqrtf(tot / (float)U_DIM + EPS_F);
    }
    __syncthreads();
    float r = rsh;
    float ge[8];
    if (GATE) {
        #pragma unroll
        for (int e = 0; e < 8; e++) ge[e] = 0.f;
    }
    for (int u = threadIdx.x; u < U_DIM; u += 256) {
        float o = hr[u] * r;
        if (WN) n[row * U_DIM + u] = o;
        bf16 hi, lo; split2(o, hi, lo);
        nhi[row * U_DIM + u] = hi; nlo[row * U_DIM + u] = lo;
        if (GATE) {
            #pragma unroll
            for (int e = 0; e < 8; e++) ge[e] = fmaf(o, __ldg(&gWl[u * 8 + e]), ge[e]);
        }
    }
    if (GATE) {
        #pragma unroll
        for (int e = 0; e < 8; e++) ge[e] = warpSum(ge[e]);
        if (lane < 8) gsl[wid][lane] = ge[lane];
        __syncthreads();
        if (threadIdx.x == 0) {
            float sl[8];
            #pragma unroll
            for (int e = 0; e < 8; e++) {
                float t = gbl[e];
                #pragma unroll
                for (int w = 0; w < 8; w++) t += gsl[w][e];
                sl[e] = t;
            }
            float mx = sl[0];
            #pragma unroll
            for (int e = 1; e < 8; e++) mx = fmaxf(mx, sl[e]);
            float ex[8], sum = 0.f;
            #pragma unroll
            for (int e = 0; e < 8; e++) { ex[e] = __expf(sl[e] - mx); sum += ex[e]; }
            float inv = 1.f / sum;
            #pragma unroll
            for (int e = 0; e < 8; e++) gate[row * 8 + e] = ex[e] * inv;
        }
    }
}

__global__ __launch_bounds__(256)
void gatemul(const float* __restrict__ n, const float* __restrict__ gate, bf16* hi, bf16* lo)
{
    long i = (long)blockIdx.x * 256 + threadIdx.x;
    int t = (int)(i / 6144), r = (int)(i % 6144);
    int e = r / 768, u = r % 768;
    float v = gate[(long)t * 8 + e] * n[(long)t * 768 + u];
    bf16 h, l; split2(v, h, l); hi[i] = h; lo[i] = l;
}
__global__ __launch_bounds__(256)
void colsum(const bf16* __restrict__ khi, const bf16* __restrict__ klo, float* ks)
{
    int gw = blockIdx.x * 8 + (threadIdx.x >> 5);   // 0..1535 = b*768+u
    int lane = threadIdx.x & 31;
    const bf16* ph = khi + (long)gw * 1024;
    const bf16* pl = klo + (long)gw * 1024;
    float s = 0.f;
    for (int t = lane; t < 1024; t += 32)
        s += __bfloat162float(ph[t]) + __bfloat162float(pl[t]);
    s = warpSum(s);
    if (lane == 0) ks[gw] = s;
}
__global__ __launch_bounds__(256)
void denk(const bf16* __restrict__ qhi, const bf16* __restrict__ qlo,
          const float* __restrict__ ks, float* den)
{
    int gw = (blockIdx.x * 256 + threadIdx.x) >> 5;
    int lane = threadIdx.x & 31;
    if (gw >= BT) return;
    int b = gw >> 10;
    const bf16* ph = qhi + (long)gw * U_DIM;
    const bf16* pl = qlo + (long)gw * U_DIM;
    const float* kb = ks + b * U_DIM;
    float s = 0.f;
    for (int u = lane; u < U_DIM; u += 32)
        s = fmaf(__bfloat162float(ph[u]) + __bfloat162float(pl[u]), kb[u], s);
    s = warpSum(s);
    if (lane == 0) den[gw] = s + EPS_F;
}
__global__ __launch_bounds__(256)
void addk(const float* __restrict__ a, const float* __restrict__ b, float* c, int n)
{
    int i = blockIdx.x * 256 + threadIdx.x;
    if (i < n) c[i] = a[i] + b[i];
}

// ---------- host ----------
static void tc(int epi, GArgs& a, int M, int N, int Z)
{
    dim3 g(N / 128, M / 128, Z);
    switch (epi) {
    case 1: mma_gemm<1><<<g, 256, DSM>>>(a); break;
    case 2: mma_gemm<2><<<g, 256, DSM>>>(a); break;
    case 7: mma_gemm<7><<<g, 256, DSM>>>(a); break;
    case 8: mma_gemm<8><<<g, 256, DSM>>>(a); break;
    }
}

extern "C" void kernel_launch(void* const* d_in, const int* in_sizes, int n_in,
                              void* d_out, int out_size)
{
    const int*   x    = (const int*)  d_in[0];
    const float* emb  = (const float*)d_in[1];
    const float* W_in = (const float*)d_in[2];
    const float* Wq   = (const float*)d_in[3];
    const float* bq   = (const float*)d_in[4];
    const float* Wk   = (const float*)d_in[5];
    const float* bk   = (const float*)d_in[6];
    const float* Wv   = (const float*)d_in[7];
    const float* bv   = (const float*)d_in[8];
    const float* gW   = (const float*)d_in[9];
    const float* gb   = (const float*)d_in[10];
    const float* eW   = (const float*)d_in[11];
    const float* eb   = (const float*)d_in[12];
    const float* fW1  = (const float*)d_in[13];
    const float* fb1  = (const float*)d_in[14];
    const float* fW2  = (const float*)d_in[15];
    const float* fb2  = (const float*)d_in[16];
    const float* Wlog = (const float*)d_in[17];
    float* out = (float*)d_out;

    cudaFuncSetAttribute(mma_gemm<1>, cudaFuncAttributeMaxDynamicSharedMemorySize, DSM);
    cudaFuncSetAttribute(mma_gemm<2>, cudaFuncAttributeMaxDynamicSharedMemorySize, DSM);
    cudaFuncSetAttribute(mma_gemm<7>, cudaFuncAttributeMaxDynamicSharedMemorySize, DSM);
    cudaFuncSetAttribute(mma_gemm<8>, cudaFuncAttributeMaxDynamicSharedMemorySize, DSM);

    bf16 *whi, *wlo, *nhi, *nlo, *xhi, *xlo, *qhi, *qlo, *kthi, *ktlo, *vthi, *vtlo;
    bf16 *kvhi, *kvlo, *f1hi, *f1lo, *amhi, *amlo;
    float *h, *h0, *hA, *hM, *n, *mo, *ksum, *den, *gate;
    cudaGetSymbolAddress((void**)&whi, g_whi);  cudaGetSymbolAddress((void**)&wlo, g_wlo);
    cudaGetSymbolAddress((void**)&h, g_h);      cudaGetSymbolAddress((void**)&h0, g_h0);
    cudaGetSymbolAddress((void**)&hA, g_hA);    cudaGetSymbolAddress((void**)&hM, g_hM);
    cudaGetSymbolAddress((void**)&n, g_n);      cudaGetSymbolAddress((void**)&mo, g_mo);
    cudaGetSymbolAddress((void**)&ksum, g_ksum);
    cudaGetSymbolAddress((void**)&den, g_den);  cudaGetSymbolAddress((void**)&gate, g_gate);
    cudaGetSymbolAddress((void**)&nhi, g_nhi);  cudaGetSymbolAddress((void**)&nlo, g_nlo);
    cudaGetSymbolAddress((void**)&xhi, g_xhi);  cudaGetSymbolAddress((void**)&xlo, g_xlo);
    cudaGetSymbolAddress((void**)&qhi, g_qhi);  cudaGetSymbolAddress((void**)&qlo, g_qlo);
    cudaGetSymbolAddress((void**)&kthi, g_kthi); cudaGetSymbolAddress((void**)&ktlo, g_ktlo);
    cudaGetSymbolAddress((void**)&vthi, g_vthi); cudaGetSymbolAddress((void**)&vtlo, g_vtlo);
    cudaGetSymbolAddress((void**)&kvhi, g_kvhi); cudaGetSymbolAddress((void**)&kvlo, g_kvlo);
    cudaGetSymbolAddress((void**)&f1hi, g_f1hi); cudaGetSymbolAddress((void**)&f1lo, g_f1lo);
    cudaGetSymbolAddress((void**)&amhi, g_amhi); cudaGetSymbolAddress((void**)&amlo, g_amlo);

    // weight prepack
    tsplit<<<dim3(24, 24, 1),   256>>>(W_in, whi + OFF_WIN, wlo + OFF_WIN, 768, 768, 0, UU, 0);
    tsplit<<<dim3(24, 24, 16),  256>>>(Wq, whi + OFF_QKV, wlo + OFF_QKV, 768, 768, 0, 3*UU, 0);
    tsplit<<<dim3(24, 24, 16),  256>>>(Wk, whi + OFF_QKV, wlo + OFF_QKV, 768, 768, 0, 3*UU, UU);
    tsplit<<<dim3(24, 24, 16),  256>>>(Wv, whi + OFF_QKV, wlo + OFF_QKV, 768, 768, 0, 3*UU, 2*UU);
    tsplit<<<dim3(24, 24, 16),  256>>>(fW1, whi + OFF_F1, wlo + OFF_F1, 768, 768, 0, UU, 0);
    tsplit<<<dim3(24, 24, 16),  256>>>(fW2, whi + OFF_F2, wlo + OFF_F2, 768, 768, 0, UU, 0);
    tsplit<<<dim3(24, 24, 128), 256>>>(eW, whi + OFF_EW, wlo + OFF_EW, 768, 768, 1, 0, 0);
    tsplit<<<dim3(1000, 24, 1), 256>>>(Wlog, whi + OFF_WLOG, wlo + OFF_WLOG, 768, 32000, 0, 0, 0);

    GArgs a;
    // h0 = emb[x] @ W_in ; h = h0
    gather_split<<<BT, 192>>>(x, emb, xhi, xlo);
    a = {}; a.Ahi = xhi; a.Alo = xlo; a.Bhi = whi + OFF_WIN; a.Blo = wlo + OFF_WIN;
    a.N = 768; a.K = 768; a.SK = 1; a.outF = h0; a.outF2 = h;
    tc(1, a, BT, 768, 1);

    for (int l = 0; l < L_DIM; l++) {
        // attention
        rms_split<0,0><<<BT, 256>>>(h, nullptr, nhi, nlo, nullptr, nullptr, nullptr);
        a = {}; a.Ahi = nhi; a.Alo = nlo;
        a.Bhi = whi + OFF_QKV + (long)l * 3 * UU; a.Blo = wlo + OFF_QKV + (long)l * 3 * UU;
        a.N = 2304; a.K = 768; a.SK = 1;
        a.bias = bq + l * U_DIM; a.bias2 = bk + l * U_DIM; a.bias3 = bv + l * U_DIM;
        a.oHi = qhi; a.oLo = qlo; a.oHi2 = kthi; a.oLo2 = ktlo; a.oHi3 = vthi; a.oLo3 = vtlo;
        tc(8, a, BT, 2304, 1);
        colsum<<<192, 256>>>(kthi, ktlo, ksum);
        denk<<<256, 256>>>(qhi, qlo, ksum, den);
        // kvT = v^T k (split-K 2, batched)
        a = {}; a.Ahi = vthi; a.Alo = vtlo; a.Bhi = kthi; a.Blo = ktlo;
        a.N = 768; a.K = 1024; a.kSplit = 512; a.SK = 2; a.aZ = TU; a.bZ = TU; a.cZ = UU;
        a.outF = mo;
        tc(2, a, 768, 768, 4);
        comb<4><<<(int)(2*UU/1024), 256>>>(mo, UU, 2, 2*UU, nullptr, nullptr, nullptr,
                                           nullptr, nullptr, nullptr, nullptr, kvhi, kvlo);
        // hA = (q @ kv)/den + h  (split-K 3, batched)
        a = {}; a.Ahi = qhi; a.Alo = qlo; a.Bhi = kvhi; a.Blo = kvlo;
        a.N = 768; a.K = 768; a.kSplit = 256; a.SK = 3; a.aZ = TU; a.bZ = UU; a.cZ = TU;
        a.outF = mo;
        tc(2, a, T_DIM, 768, 6);
        comb<0><<<(int)(HN/1024), 256>>>(mo, TU, 3, HN, nullptr, den, h,
                                         nullptr, nullptr, nullptr, hA, nullptr, nullptr);
        // moe
        rms_split<1,1><<<BT, 256>>>(hA, n, nhi, nlo,
                                    gW + (long)l * U_DIM * E_DIM, gb + l * E_DIM, gate);
        gatemul<<<(int)(BT * 6144 / 256), 256>>>(n, gate, amhi, amlo);
        a = {}; a.Ahi = amhi; a.Alo = amlo;
        a.Bhi = whi + OFF_EW + (long)l * 8 * UU; a.Blo = wlo + OFF_EW + (long)l * 8 * UU;
        a.N = 768; a.K = 6144; a.kSplit = 2048; a.SK = 3; a.cZ = HN; a.outF = mo;
        tc(2, a, BT, 768, 3);
        comb<2><<<(int)(HN/1024), 256>>>(mo, HN, 3, HN, nullptr, nullptr, nullptr,
                                         nullptr, gate, eb + (long)l * E_DIM * U_DIM,
                                         hM, nullptr, nullptr);
        // ffn
        rms_split<0,0><<<BT, 256>>>(hM, nullptr, nhi, nlo, nullptr, nullptr, nullptr);
        a = {}; a.Ahi = nhi; a.Alo = nlo;
        a.Bhi = whi + OFF_F1 + (long)l * UU; a.Blo = wlo + OFF_F1 + (long)l * UU;
        a.N = 768; a.K = 768; a.kSplit = 256; a.SK = 3; a.cZ = HN; a.outF = mo;
        tc(2, a, BT, 768, 3);
        comb<1><<<(int)(HN/1024), 256>>>(mo, HN, 3, HN, fb1 + l * U_DIM, nullptr, nullptr,
                                         nullptr, nullptr, nullptr, nullptr, f1hi, f1lo);
        a = {}; a.Ahi = f1hi; a.Alo = f1lo;
        a.Bhi = whi + OFF_F2 + (long)l * UU; a.Blo = wlo + OFF_F2 + (long)l * UU;
        a.N = 768; a.K = 768; a.kSplit = 256; a.SK = 3; a.cZ = HN; a.outF = mo;
        tc(2, a, BT, 768, 3);
        comb<3><<<(int)(HN/1024), 256>>>(mo, HN, 3, HN, fb2 + l * U_DIM, nullptr, hM,
                                         h, nullptr, nullptr, h, nullptr, nullptr);
    }

    // final norms + logits
    rms_split<0,1><<<BT, 256>>>(h, n, nhi, nlo, nullptr, nullptr, nullptr);
    addk<<<(int)(HN/256), 256>>>(n, h0, hA, (int)HN);
    rms_split<0,0><<<BT, 256>>>(hA, nullptr, nhi, nlo, nullptr, nullptr, nullptr);
    a = {}; a.Ahi = nhi; a.Alo = nlo; a.Bhi = whi + OFF_WLOG; a.Blo = wlo + OFF_WLOG;
    a.N = 32000; a.K = 768; a.SK = 1; a.outF = out;
    tc(7, a, BT, 32000, 1);
}

// round 9
// speedup vs baseline: 2.7666x; 1.0181x over previous
#include <cuda_runtime.h>
#include <cuda_bf16.h>
#include <cuda_fp16.h>
#include <cstdint>

#define U_DIM 768
#define T_DIM 1024
#define B_DIM 2
#define BT    2048
#define E_DIM 8
#define L_DIM 16
#define V_DIM 32000
#define EPS_F 1e-6f
#define UU    589824L
#define TU    786432L
#define HN    1572864L

#define OFF_WIN  0L
#define OFF_QKV  (UU)
#define OFF_F1   (OFF_QKV + 48L*UU)
#define OFF_F2   (OFF_F1 + 16L*UU)
#define OFF_EW   (OFF_F2 + 16L*UU)
#define OFF_WLOG (OFF_EW + 128L*UU)
#define W_TOTAL  (OFF_WLOG + 32000L*768L)

typedef __nv_bfloat16 bf16;

__device__ bf16 g_whi[W_TOTAL];
__device__ bf16 g_wlo[W_TOTAL];
__device__ float g_h[HN], g_h0[HN], g_hA[HN], g_hM[HN], g_n[HN];
__device__ float g_mo[3*HN];
__device__ float g_ksum[B_DIM*U_DIM], g_den[BT], g_gate[BT*E_DIM];
__device__ bf16 g_nhi[HN],  g_nlo[HN];
__device__ bf16 g_xhi[HN],  g_xlo[HN];
__device__ bf16 g_qhi[HN],  g_qlo[HN];
__device__ bf16 g_kthi[HN], g_ktlo[HN];
__device__ bf16 g_vthi[HN], g_vtlo[HN];
__device__ bf16 g_kvhi[B_DIM*UU], g_kvlo[B_DIM*UU];
__device__ bf16 g_f1hi[HN], g_f1lo[HN];
__device__ bf16 g_amhi[BT*6144L], g_amlo[BT*6144L];

__device__ __forceinline__ uint32_t smem_u32(const void* p) {
    uint32_t a;
    asm("{ .reg .u64 t; cvta.to.shared.u64 t, %1; cvt.u32.u64 %0, t; }" : "=r"(a) : "l"(p));
    return a;
}
__device__ __forceinline__ void split2(float x, bf16& hi, bf16& lo) {
    hi = __float2bfloat16(x);
    lo = __float2bfloat16(x - __bfloat162float(hi));
}
__device__ __forceinline__ void split2h(float x, __half& hi, __half& lo) {
    hi = __float2half(x);
    lo = __float2half(x - __half2float(hi));
}
__device__ __forceinline__ float warpSum(float v) {
    #pragma unroll
    for (int o = 16; o > 0; o >>= 1) v += __shfl_xor_sync(0xffffffffu, v, o);
    return v;
}

struct GArgs {
    const bf16 *Ahi, *Alo, *Bhi, *Blo;
    int N, K, kSplit, SK;
    long aZ, bZ, cZ;
    const float *bias, *bias2, *bias3;
    float *outF, *outF2;
    bf16 *oHi, *oLo, *oHi2, *oLo2, *oHi3, *oLo3;
};

#define ROWS 72
#define TB   (128 * ROWS * 2)
#define DSM  (8 * TB)

// EPI: 1 out(+copy), 2 partial, 7 logits x2, 8 qkv.  P2: fp16 2-pass (drop A-lo)
template<int EPI, int P2>
__global__ __launch_bounds__(256)
void mma_gemm(GArgs g)
{
    extern __shared__ char smem[];
    uint32_t sb = smem_u32(smem);
    const int tid = threadIdx.x, wid = tid >> 5, lane = tid & 31;
    const int wm = wid >> 2, wn = wid & 3;
    const int z = blockIdx.z;
    const int zB = g.SK > 1 ? z / g.SK : z;
    const int zS = g.SK > 1 ? z % g.SK : 0;
    const int row0 = blockIdx.y * 128, col0 = blockIdx.x * 128;
    const int Nn = g.N, K = g.K;

    const bf16* Ahi = g.Ahi + (long)zB * g.aZ;
    const bf16* Alo = g.Alo + (long)zB * g.aZ;
    const bf16* Bhi = g.Bhi + (long)zB * g.bZ;
    const bf16* Blo = g.Blo + (long)zB * g.bZ;
    const int kbase = g.kSplit ? zS * g.kSplit : 0;
    const int CH = (g.kSplit ? g.kSplit : K) >> 6;

    float d[4][4][4];
    #pragma unroll
    for (int a = 0; a < 4; a++)
        #pragma unroll
        for (int b = 0; b < 4; b++)
            #pragma unroll
            for (int c = 0; c < 4; c++) d[a][b][c] = 0.f;

    auto issue = [&](int c, int s) {
        int k0 = kbase + (c << 6);
        const bf16* srcs[4] = {
            Ahi + (long)row0 * K + k0, Alo + (long)row0 * K + k0,
            Bhi + (long)col0 * K + k0, Blo + (long)col0 * K + k0 };
        #pragma unroll
        for (int t = 0; t < 4; t++) {
            if (P2 && t == 1) continue;
            uint32_t dst = sb + (uint32_t)(s * 4 + t) * TB;
            #pragma unroll
            for (int i = 0; i < 4; i++) {
                int idx = tid + (i << 8);
                int r = idx >> 3, cc = idx & 7;
                uint32_t doff = (uint32_t)(r * ROWS + cc * 8) * 2;
                const void* sp = srcs[t] + (long)r * K + cc * 8;
                asm volatile("cp.async.cg.shared.global [%0], [%1], 16;"
                             :: "r"(dst + doff), "l"(sp));
            }
        }
        asm volatile("cp.async.commit_group;");
    };

    issue(0, 0);
    for (int c = 0; c < CH; c++) {
        int s = c & 1;
        if (c + 1 < CH) { issue(c + 1, s ^ 1); asm volatile("cp.async.wait_group 1;"); }
        else            { asm volatile("cp.async.wait_group 0;"); }
        __syncthreads();
        uint32_t bAH = sb + (uint32_t)(s * 4 + 0) * TB;
        uint32_t bAL = sb + (uint32_t)(s * 4 + 1) * TB;
        uint32_t bBH = sb + (uint32_t)(s * 4 + 2) * TB;
        uint32_t bBL = sb + (uint32_t)(s * 4 + 3) * TB;
        #pragma unroll
        for (int ks = 0; ks < 4; ks++) {
            int k16 = ks * 16;
            int aoff = (wm * 64 + (lane & 15)) * ROWS + k16 + ((lane >> 4) << 3);
            int boff = (wn * 32 + (lane & 7)) * ROWS + k16 + (((lane >> 3) & 1) << 3);
            uint32_t af[4][4], af2[4][4], bf_[4][2];
            #pragma unroll
            for (int mt = 0; mt < 4; mt++) {
                uint32_t ad = bAH + (uint32_t)(aoff + mt * 16 * ROWS) * 2;
                asm volatile("ldmatrix.sync.aligned.m8n8.x4.shared.b16 {%0,%1,%2,%3}, [%4];"
                    : "=r"(af[mt][0]), "=r"(af[mt][1]), "=r"(af[mt][2]), "=r"(af[mt][3]) : "r"(ad));
            }
            #pragma unroll
            for (int nt = 0; nt < 4; nt++) {
                uint32_t bd = bBH + (uint32_t)(boff + nt * 8 * ROWS) * 2;
                asm volatile("ldmatrix.sync.aligned.m8n8.x2.shared.b16 {%0,%1}, [%2];"
                    : "=r"(bf_[nt][0]), "=r"(bf_[nt][1]) : "r"(bd));
            }
            // pass 1: AH x BH
            #pragma unroll
            for (int mt = 0; mt < 4; mt++)
                #pragma unroll
                for (int nt = 0; nt < 4; nt++) {
                    if (P2)
                        asm volatile("mma.sync.aligned.m16n8k16.row.col.f32.f16.f16.f32 "
                            "{%0,%1,%2,%3}, {%4,%5,%6,%7}, {%8,%9}, {%0,%1,%2,%3};"
                            : "+f"(d[mt][nt][0]), "+f"(d[mt][nt][1]), "+f"(d[mt][nt][2]), "+f"(d[mt][nt][3])
                            : "r"(af[mt][0]), "r"(af[mt][1]), "r"(af[mt][2]), "r"(af[mt][3]),
                              "r"(bf_[nt][0]), "r"(bf_[nt][1]));
                    else
                        asm volatile("mma.sync.aligned.m16n8k16.row.col.f32.bf16.bf16.f32 "
                            "{%0,%1,%2,%3}, {%4,%5,%6,%7}, {%8,%9}, {%0,%1,%2,%3};"
                            : "+f"(d[mt][nt][0]), "+f"(d[mt][nt][1]), "+f"(d[mt][nt][2]), "+f"(d[mt][nt][3])
                            : "r"(af[mt][0]), "r"(af[mt][1]), "r"(af[mt][2]), "r"(af[mt][3]),
                              "r"(bf_[nt][0]), "r"(bf_[nt][1]));
                }
            if (!P2) {
                // pass 2: AL x BH (reuse BH fragments)
                #pragma unroll
                for (int mt = 0; mt < 4; mt++) {
                    uint32_t ad = bAL + (uint32_t)(aoff + mt * 16 * ROWS) * 2;
                    asm volatile("ldmatrix.sync.aligned.m8n8.x4.shared.b16 {%0,%1,%2,%3}, [%4];"
                        : "=r"(af2[mt][0]), "=r"(af2[mt][1]), "=r"(af2[mt][2]), "=r"(af2[mt][3]) : "r"(ad));
                }
                #pragma unroll
                for (int mt = 0; mt < 4; mt++)
                    #pragma unroll
                    for (int nt = 0; nt < 4; nt++)
                        asm volatile("mma.sync.aligned.m16n8k16.row.col.f32.bf16.bf16.f32 "
                            "{%0,%1,%2,%3}, {%4,%5,%6,%7}, {%8,%9}, {%0,%1,%2,%3};"
                            : "+f"(d[mt][nt][0]), "+f"(d[mt][nt][1]), "+f"(d[mt][nt][2]), "+f"(d[mt][nt][3])
                            : "r"(af2[mt][0]), "r"(af2[mt][1]), "r"(af2[mt][2]), "r"(af2[mt][3]),
                              "r"(bf_[nt][0]), "r"(bf_[nt][1]));
            }
            // pass 3: AH x BL (reuse AH fragments)
            #pragma unroll
            for (int nt = 0; nt < 4; nt++) {
                uint32_t bd = bBL + (uint32_t)(boff + nt * 8 * ROWS) * 2;
                asm volatile("ldmatrix.sync.aligned.m8n8.x2.shared.b16 {%0,%1}, [%2];"
                    : "=r"(bf_[nt][0]), "=r"(bf_[nt][1]) : "r"(bd));
            }
            #pragma unroll
            for (int mt = 0; mt < 4; mt++)
                #pragma unroll
                for (int nt = 0; nt < 4; nt++) {
                    if (P2)
                        asm volatile("mma.sync.aligned.m16n8k16.row.col.f32.f16.f16.f32 "
                            "{%0,%1,%2,%3}, {%4,%5,%6,%7}, {%8,%9}, {%0,%1,%2,%3};"
                            : "+f"(d[mt][nt][0]), "+f"(d[mt][nt][1]), "+f"(d[mt][nt][2]), "+f"(d[mt][nt][3])
                            : "r"(af[mt][0]), "r"(af[mt][1]), "r"(af[mt][2]), "r"(af[mt][3]),
                              "r"(bf_[nt][0]), "r"(bf_[nt][1]));
                    else
                        asm volatile("mma.sync.aligned.m16n8k16.row.col.f32.bf16.bf16.f32 "
                            "{%0,%1,%2,%3}, {%4,%5,%6,%7}, {%8,%9}, {%0,%1,%2,%3};"
                            : "+f"(d[mt][nt][0]), "+f"(d[mt][nt][1]), "+f"(d[mt][nt][2]), "+f"(d[mt][nt][3])
                            : "r"(af[mt][0]), "r"(af[mt][1]), "r"(af[mt][2]), "r"(af[mt][3]),
                              "r"(bf_[nt][0]), "r"(bf_[nt][1]));
                }
        }
        __syncthreads();
    }

    // ---------------- epilogues ----------------
    if (EPI == 8) {
        const int blkN = col0 / 768;
        const int cc0  = col0 - blkN * 768;
        if (blkN == 0) {
            #pragma unroll
            for (int mt = 0; mt < 4; mt++)
                #pragma unroll
                for (int half = 0; half < 2; half++) {
                    int rg = row0 + wm * 64 + mt * 16 + (lane >> 2) + half * 8;
                    #pragma unroll
                    for (int nt = 0; nt < 4; nt++) {
                        int col = cc0 + wn * 32 + nt * 8 + 2 * (lane & 3);
                        float t0 = d[mt][nt][half*2+0] + __ldg(&g.bias[col]);
                        float t1 = d[mt][nt][half*2+1] + __ldg(&g.bias[col+1]);
                        float o0 = (t0 > 0.f) ? (t0 + 1.f) : __expf(t0);
                        float o1 = (t1 > 0.f) ? (t1 + 1.f) : __expf(t1);
                        bf16 h0b,l0b,h1b,l1b; split2(o0,h0b,l0b); split2(o1,h1b,l1b);
                        __nv_bfloat162 ph; ph.x=h0b; ph.y=h1b;
                        __nv_bfloat162 pl; pl.x=l0b; pl.y=l1b;
                        long idx = (long)rg * 768 + col;
                        *(__nv_bfloat162*)(g.oHi + idx) = ph;
                        *(__nv_bfloat162*)(g.oLo + idx) = pl;
                    }
                }
        } else {
            const float* bp = (blkN == 1) ? g.bias2 : g.bias3;
            float* tile = (float*)smem;
            #pragma unroll
            for (int mt = 0; mt < 4; mt++)
                #pragma unroll
                for (int nt = 0; nt < 4; nt++)
                    #pragma unroll
                    for (int half = 0; half < 2; half++)
                        #pragma unroll
                        for (int jj = 0; jj < 2; jj++) {
                            int r = wm*64 + mt*16 + (lane>>2) + half*8;
                            int cl = wn*32 + nt*8 + 2*(lane&3) + jj;
                            float t = d[mt][nt][half*2+jj] + __ldg(&bp[cc0 + cl]);
                            if (blkN == 1) t = (t > 0.f) ? (t + 1.f) : __expf(t);
                            tile[r * 130 + cl] = t;
                        }
            __syncthreads();
            bf16* dh = (blkN == 1) ? g.oHi2 : g.oHi3;
            bf16* dl = (blkN == 1) ? g.oLo2 : g.oLo3;
            int u_l = tid & 127, th = tid >> 7;
            int bb = row0 >> 10, t0 = row0 & 1023;
            long rowbase = ((long)(bb * 768 + cc0 + u_l)) * 1024 + t0 + th * 64;
            uint32_t hb[32], lb[32];
            #pragma unroll
            for (int j = 0; j < 64; j += 2) {
                float v0 = tile[(th*64 + j) * 130 + u_l];
                float v1 = tile[(th*64 + j + 1) * 130 + u_l];
                bf16 h0b,l0b,h1b,l1b; split2(v0,h0b,l0b); split2(v1,h1b,l1b);
                __nv_bfloat162 ph; ph.x=h0b; ph.y=h1b;
                __nv_bfloat162 pl; pl.x=l0b; pl.y=l1b;
                hb[j>>1] = *(uint32_t*)&ph; lb[j>>1] = *(uint32_t*)&pl;
            }
            uint4* dh4 = (uint4*)(dh + rowbase);
            uint4* dl4 = (uint4*)(dl + rowbase);
            #pragma unroll
            for (int i = 0; i < 8; i++) { dh4[i] = ((uint4*)hb)[i]; dl4[i] = ((uint4*)lb)[i]; }
        }
        return;
    }

    float* outF = g.outF + (long)z * g.cZ;
    #pragma unroll
    for (int mt = 0; mt < 4; mt++)
        #pragma unroll
        for (int half = 0; half < 2; half++) {
            int rg = row0 + wm * 64 + mt * 16 + (lane >> 2) + half * 8;
            #pragma unroll
            for (int nt = 0; nt < 4; nt++) {
                int col = col0 + wn * 32 + nt * 8 + 2 * (lane & 3);
                #pragma unroll
                for (int jj = 0; jj < 2; jj++) {
                    float x = d[mt][nt][half*2+jj];
                    long idx = (long)rg * Nn + col + jj;
                    if (EPI == 2) outF[idx] = x;
                    else if (EPI == 7) outF[idx] = x * 2.0f;
                    else { outF[idx] = x; if (g.outF2) g.outF2[idx] = x; }
                }
            }
        }
}

// ---------- row-fused combines: sum 3 partials + epilogue + RMS(+gate) ----------
// MODE 0: attn (den,res h) -> n,nhi,nlo,gate ; MODE 1: moe (+gate*eb) -> hM,nhi,nlo
// MODE 2: ffn2 sigmoid + hM + h -> h,n,nhi,nlo
template<int MODE>
__global__ __launch_bounds__(256)
void combA(const float* __restrict__ mo, const float* __restrict__ den,
           const float* __restrict__ hOld, const float* __restrict__ hMin,
           const float* __restrict__ bias, const float* __restrict__ eb,
           const float* __restrict__ gWl, const float* __restrict__ gbl,
           const float* __restrict__ gateIn,
           float* hMout, float* hOut, float* nOut, float* gateOut,
           bf16* nhi, bf16* nlo)
{
    __shared__ float row[768];
    __shared__ float red[8]; __shared__ float rsh; __shared__ float gsl[8][8];
    int r = blockIdx.x, tid = threadIdx.x;
    int wid = tid >> 5, lane = tid & 31;
    int b = r >> 10, t = r & 1023;
    for (int u = tid; u < 768; u += 256) {
        float v;
        if (MODE == 0) {
            long base = (long)(b * 3) * TU + (long)t * 768 + u;
            v = mo[base] + mo[base + TU] + mo[base + 2 * TU];
            v = v / den[r] + hOld[(long)r * 768 + u];
        } else {
            long base = (long)r * 768 + u;
            v = mo[base] + mo[base + HN] + mo[base + 2 * HN];
            if (MODE == 1) {
                float bm = 0.f;
                #pragma unroll
                for (int e = 0; e < 8; e++)
                    bm = fmaf(gateIn[(long)r * 8 + e], __ldg(&eb[e * 768 + u]), bm);
                v += bm;
                hMout[base] = v;
            } else {
                float tt = v + __ldg(&bias[u]);
                v = 1.f / (1.f + __expf(-tt)) + hMin[base] + hOld[base];
                hOut[base] = v;
            }
        }
        row[u] = v;
    }
    __syncthreads();
    float s = 0.f;
    for (int u = tid; u < 768; u += 256) { float x = row[u]; s = fmaf(x, x, s); }
    s = warpSum(s);
    if (lane == 0) red[wid] = s;
    __syncthreads();
    if (tid == 0) {
        float tot = 0.f;
        #pragma unroll
        for (int i = 0; i < 8; i++) tot += red[i];
        rsh = rsqrtf(tot / 768.f + EPS_F);
    }
    __syncthreads();
    float rr = rsh;
    float ge[8];
    if (MODE == 0) {
        #pragma unroll
        for (int e = 0; e < 8; e++) ge[e] = 0.f;
    }
    for (int u = tid; u < 768; u += 256) {
        float o = row[u] * rr;
        if (MODE != 1) nOut[(long)r * 768 + u] = o;
        bf16 hi, lo; split2(o, hi, lo);
        nhi[(long)r * 768 + u] = hi; nlo[(long)r * 768 + u] = lo;
        if (MODE == 0) {
            #pragma unroll
            for (int e = 0; e < 8; e++) ge[e] = fmaf(o, __ldg(&gWl[u * 8 + e]), ge[e]);
        }
    }
    if (MODE == 0) {
        #pragma unroll
        for (int e = 0; e < 8; e++) ge[e] = warpSum(ge[e]);
        if (lane < 8) gsl[wid][lane] = ge[lane];
        __syncthreads();
        if (tid == 0) {
            float sl[8];
            #pragma unroll
            for (int e = 0; e < 8; e++) {
                float tt = gbl[e];
                #pragma unroll
                for (int w = 0; w < 8; w++) tt += gsl[w][e];
                sl[e] = tt;
            }
            float mx = sl[0];
            #pragma unroll
            for (int e = 1; e < 8; e++) mx = fmaxf(mx, sl[e]);
            float ex[8], sum = 0.f;
            #pragma unroll
            for (int e = 0; e < 8; e++) { ex[e] = __expf(sl[e] - mx); sum += ex[e]; }
            float inv = 1.f / sum;
            #pragma unroll
            for (int e = 0; e < 8; e++) gateOut[(long)r * 8 + e] = ex[e] * inv;
        }
    }
}

// elementwise combines kept: MODE 1 f1-sig-split, MODE 4 kv-split
template<int MODE>
__global__ __launch_bounds__(256)
void comb(const float* __restrict__ p, long segZ, int ns, long total,
          const float* __restrict__ bias, bf16* oHi, bf16* oLo)
{
    long i4 = ((long)blockIdx.x * 256 + threadIdx.x) * 4;
    if (i4 >= total) return;
    long base = (i4 / segZ) * (long)ns * segZ + (i4 % segZ);
    float4 s = *(const float4*)(p + base);
    float4 s1 = *(const float4*)(p + base + segZ);
    s.x += s1.x; s.y += s1.y; s.z += s1.z; s.w += s1.w;
    if (ns == 3) {
        float4 s2 = *(const float4*)(p + base + 2 * segZ);
        s.x += s2.x; s.y += s2.y; s.z += s2.z; s.w += s2.w;
    }
    float v[4] = {s.x, s.y, s.z, s.w};
    int col = (int)(i4 % 768);
    bf16 hh[4], ll[4];
    #pragma unroll
    for (int j = 0; j < 4; j++) {
        float o = v[j];
        if (MODE == 1) { float t = o + __ldg(&bias[col + j]); o = 1.f / (1.f + __expf(-t)); }
        split2(o, hh[j], ll[j]);
    }
    *(uint2*)(oHi + i4) = *(uint2*)hh;
    *(uint2*)(oLo + i4) = *(uint2*)ll;
}

// ---------- prepack ----------
__global__ __launch_bounds__(256)
void tsplit(const float* __restrict__ src, bf16* dhi, bf16* dlo, int K, int N,
            int mode, long outZ, long rowOff)
{
    __shared__ float t[32][33];
    int z = blockIdx.z;
    const float* s = src + (long)z * K * N;
    long dbase; int dld;
    if (mode == 1) { int l = z >> 3, e = z & 7; dbase = (long)l * 8 * UU + (long)e * U_DIM; dld = 6144; }
    else { dbase = (long)z * outZ + rowOff; dld = K; }
    int n0 = blockIdx.x * 32, k0 = blockIdx.y * 32;
    int tx = threadIdx.x & 31, ty = threadIdx.x >> 5;
    #pragma unroll
    for (int i = 0; i < 32; i += 8) t[ty + i][tx] = s[(long)(k0 + ty + i) * N + n0 + tx];
    __syncthreads();
    #pragma unroll
    for (int i = 0; i < 32; i += 8) {
        float v = t[tx][ty + i];
        long di = dbase + (long)(n0 + ty + i) * dld + k0 + tx;
        if (mode == 2) {
            __half hi, lo; split2h(v, hi, lo);
            ((__half*)dhi)[di] = hi; ((__half*)dlo)[di] = lo;
        } else {
            bf16 hi, lo; split2(v, hi, lo);
            dhi[di] = hi; dlo[di] = lo;
        }
    }
}

// ---------- small kernels ----------
__global__ __launch_bounds__(192)
void gather_split(const int* __restrict__ x, const float* __restrict__ emb, bf16* xhi, bf16* xlo)
{
    int row = blockIdx.x, tok = x[row];
    const float* s = emb + (long)tok * U_DIM;
    for (int i = threadIdx.x; i < U_DIM; i += 192) {
        bf16 hi, lo; split2(s[i], hi, lo);
        xhi[(long)row * U_DIM + i] = hi; xlo[(long)row * U_DIM + i] = lo;
    }
}
// HALF=1: write fp16 split instead of bf16
template<int HALF>
__global__ __launch_bounds__(256)
void rms_split(const float* __restrict__ h, bf16* nhi, bf16* nlo)
{
    long row = blockIdx.x;
    const float* hr = h + row * U_DIM;
    float s = 0.f;
    for (int u = threadIdx.x; u < U_DIM; u += 256) { float t = hr[u]; s = fmaf(t, t, s); }
    s = warpSum(s);
    __shared__ float red[8]; __shared__ float rsh;
    int wid = threadIdx.x >> 5, lane = threadIdx.x & 31;
    if (lane == 0) red[wid] = s;
    __syncthreads();
    if (threadIdx.x == 0) {
        float tot = 0.f;
        #pragma unroll
        for (int i = 0; i < 8; i++) tot += red[i];
        rsh = rsqrtf(tot / (float)U_DIM + EPS_F);
    }
    __syncthreads();
    float r = rsh;
    for (int u = threadIdx.x; u < U_DIM; u += 256) {
        float o = hr[u] * r;
        if (HALF) {
            __half hi, lo; split2h(o, hi, lo);
            ((__half*)nhi)[row * U_DIM + u] = hi;
            ((__half*)nlo)[row * U_DIM + u] = lo;
        } else {
            bf16 hi, lo; split2(o, hi, lo);
            nhi[row * U_DIM + u] = hi; nlo[row * U_DIM + u] = lo;
        }
    }
}
__global__ __launch_bounds__(256)
void gatemul(const float* __restrict__ n, const float* __restrict__ gate, bf16* hi, bf16* lo)
{
    long i = (long)blockIdx.x * 256 + threadIdx.x;
    int t = (int)(i / 6144), r = (int)(i % 6144);
    int e = r / 768, u = r % 768;
    float v = gate[(long)t * 8 + e] * n[(long)t * 768 + u];
    bf16 h, l; split2(v, h, l); hi[i] = h; lo[i] = l;
}
__global__ __launch_bounds__(256)
void colsum(const bf16* __restrict__ khi, const bf16* __restrict__ klo, float* ks)
{
    int gw = blockIdx.x * 8 + (threadIdx.x >> 5);
    int lane = threadIdx.x & 31;
    const bf16* ph = khi + (long)gw * 1024;
    const bf16* pl = klo + (long)gw * 1024;
    float s = 0.f;
    for (int t = lane; t < 1024; t += 32)
        s += __bfloat162float(ph[t]) + __bfloat162float(pl[t]);
    s = warpSum(s);
    if (lane == 0) ks[gw] = s;
}
__global__ __launch_bounds__(256)
void denk(const bf16* __restrict__ qhi, const bf16* __restrict__ qlo,
          const float* __restrict__ ks, float* den)
{
    int gw = (blockIdx.x * 256 + threadIdx.x) >> 5;
    int lane = threadIdx.x & 31;
    if (gw >= BT) return;
    int b = gw >> 10;
    const bf16* ph = qhi + (long)gw * U_DIM;
    const bf16* pl = qlo + (long)gw * U_DIM;
    const float* kb = ks + b * U_DIM;
    float s = 0.f;
    for (int u = lane; u < U_DIM; u += 32)
        s = fmaf(__bfloat162float(ph[u]) + __bfloat162float(pl[u]), kb[u], s);
    s = warpSum(s);
    if (lane == 0) den[gw] = s + EPS_F;
}
__global__ __launch_bounds__(256)
void addk(const float* __restrict__ a, const float* __restrict__ b, float* c, int n)
{
    int i = blockIdx.x * 256 + threadIdx.x;
    if (i < n) c[i] = a[i] + b[i];
}

// ---------- host ----------
static void tc(int epi, GArgs& a, int M, int N, int Z)
{
    dim3 g(N / 128, M / 128, Z);
    switch (epi) {
    case 1: mma_gemm<1,0><<<g, 256, DSM>>>(a); break;
    case 2: mma_gemm<2,0><<<g, 256, DSM>>>(a); break;
    case 7: mma_gemm<7,1><<<g, 256, DSM>>>(a); break;   // fp16 2-pass logits
    case 8: mma_gemm<8,0><<<g, 256, DSM>>>(a); break;
    }
}

extern "C" void kernel_launch(void* const* d_in, const int* in_sizes, int n_in,
                              void* d_out, int out_size)
{
    const int*   x    = (const int*)  d_in[0];
    const float* emb  = (const float*)d_in[1];
    const float* W_in = (const float*)d_in[2];
    const float* Wq   = (const float*)d_in[3];
    const float* bq   = (const float*)d_in[4];
    const float* Wk   = (const float*)d_in[5];
    const float* bk   = (const float*)d_in[6];
    const float* Wv   = (const float*)d_in[7];
    const float* bv   = (const float*)d_in[8];
    const float* gW   = (const float*)d_in[9];
    const float* gb   = (const float*)d_in[10];
    const float* eW   = (const float*)d_in[11];
    const float* eb   = (const float*)d_in[12];
    const float* fW1  = (const float*)d_in[13];
    const float* fb1  = (const float*)d_in[14];
    const float* fW2  = (const float*)d_in[15];
    const float* fb2  = (const float*)d_in[16];
    const float* Wlog = (const float*)d_in[17];
    float* out = (float*)d_out;

    cudaFuncSetAttribute((const void*)mma_gemm<1,0>, cudaFuncAttributeMaxDynamicSharedMemorySize, DSM);
    cudaFuncSetAttribute((const void*)mma_gemm<2,0>, cudaFuncAttributeMaxDynamicSharedMemorySize, DSM);
    cudaFuncSetAttribute((const void*)mma_gemm<7,1>, cudaFuncAttributeMaxDynamicSharedMemorySize, DSM);
    cudaFuncSetAttribute((const void*)mma_gemm<8,0>, cudaFuncAttributeMaxDynamicSharedMemorySize, DSM);

    bf16 *whi, *wlo, *nhi, *nlo, *xhi, *xlo, *qhi, *qlo, *kthi, *ktlo, *vthi, *vtlo;
    bf16 *kvhi, *kvlo, *f1hi, *f1lo, *amhi, *amlo;
    float *h, *h0, *hA, *hM, *n, *mo, *ksum, *den, *gate;
    cudaGetSymbolAddress((void**)&whi, g_whi);  cudaGetSymbolAddress((void**)&wlo, g_wlo);
    cudaGetSymbolAddress((void**)&h, g_h);      cudaGetSymbolAddress((void**)&h0, g_h0);
    cudaGetSymbolAddress((void**)&hA, g_hA);    cudaGetSymbolAddress((void**)&hM, g_hM);
    cudaGetSymbolAddress((void**)&n, g_n);      cudaGetSymbolAddress((void**)&mo, g_mo);
    cudaGetSymbolAddress((void**)&ksum, g_ksum);
    cudaGetSymbolAddress((void**)&den, g_den);  cudaGetSymbolAddress((void**)&gate, g_gate);
    cudaGetSymbolAddress((void**)&nhi, g_nhi);  cudaGetSymbolAddress((void**)&nlo, g_nlo);
    cudaGetSymbolAddress((void**)&xhi, g_xhi);  cudaGetSymbolAddress((void**)&xlo, g_xlo);
    cudaGetSymbolAddress((void**)&qhi, g_qhi);  cudaGetSymbolAddress((void**)&qlo, g_qlo);
    cudaGetSymbolAddress((void**)&kthi, g_kthi); cudaGetSymbolAddress((void**)&ktlo, g_ktlo);
    cudaGetSymbolAddress((void**)&vthi, g_vthi); cudaGetSymbolAddress((void**)&vtlo, g_vtlo);
    cudaGetSymbolAddress((void**)&kvhi, g_kvhi); cudaGetSymbolAddress((void**)&kvlo, g_kvlo);
    cudaGetSymbolAddress((void**)&f1hi, g_f1hi); cudaGetSymbolAddress((void**)&f1lo, g_f1lo);
    cudaGetSymbolAddress((void**)&amhi, g_amhi); cudaGetSymbolAddress((void**)&amlo, g_amlo);

    GArgs a;
    // prepack ordered so launch #5 is the h0 GEMM (ncu -s 5 -c 1 lands on it)
    tsplit<<<dim3(24, 24, 16),  256>>>(Wq, whi + OFF_QKV, wlo + OFF_QKV, 768, 768, 0, 3*UU, 0);       // 0
    tsplit<<<dim3(24, 24, 16),  256>>>(Wk, whi + OFF_QKV, wlo + OFF_QKV, 768, 768, 0, 3*UU, UU);      // 1
    tsplit<<<dim3(24, 24, 16),  256>>>(Wv, whi + OFF_QKV, wlo + OFF_QKV, 768, 768, 0, 3*UU, 2*UU);    // 2
    tsplit<<<dim3(24, 24, 1),   256>>>(W_in, whi + OFF_WIN, wlo + OFF_WIN, 768, 768, 0, UU, 0);       // 3
    gather_split<<<BT, 192>>>(x, emb, xhi, xlo);                                                       // 4
    a = {}; a.Ahi = xhi; a.Alo = xlo; a.Bhi = whi + OFF_WIN; a.Blo = wlo + OFF_WIN;
    a.N = 768; a.K = 768; a.SK = 1; a.outF = h0; a.outF2 = h;
    tc(1, a, BT, 768, 1);                                                                              // 5
    tsplit<<<dim3(24, 24, 16),  256>>>(fW1, whi + OFF_F1, wlo + OFF_F1, 768, 768, 0, UU, 0);
    tsplit<<<dim3(24, 24, 16),  256>>>(fW2, whi + OFF_F2, wlo + OFF_F2, 768, 768, 0, UU, 0);
    tsplit<<<dim3(24, 24, 128), 256>>>(eW, whi + OFF_EW, wlo + OFF_EW, 768, 768, 1, 0, 0);
    tsplit<<<dim3(1000, 24, 1), 256>>>(Wlog, whi + OFF_WLOG, wlo + OFF_WLOG, 768, 32000, 2, 0, 0);    // fp16
    rms_split<0><<<BT, 256>>>(h, nhi, nlo);   // initial rms for layer 0

    for (int l = 0; l < L_DIM; l++) {
        // attention
        a = {}; a.Ahi = nhi; a.Alo = nlo;
        a.Bhi = whi + OFF_QKV + (long)l * 3 * UU; a.Blo = wlo + OFF_QKV + (long)l * 3 * UU;
        a.N = 2304; a.K = 768; a.SK = 1;
        a.bias = bq + l * U_DIM; a.bias2 = bk + l * U_DIM; a.bias3 = bv + l * U_DIM;
        a.oHi = qhi; a.oLo = qlo; a.oHi2 = kthi; a.oLo2 = ktlo; a.oHi3 = vthi; a.oLo3 = vtlo;
        tc(8, a, BT, 2304, 1);
        colsum<<<192, 256>>>(kthi, ktlo, ksum);
        denk<<<256, 256>>>(qhi, qlo, ksum, den);
        a = {}; a.Ahi = vthi; a.Alo = vtlo; a.Bhi = kthi; a.Blo = ktlo;
        a.N = 768; a.K = 1024; a.kSplit = 512; a.SK = 2; a.aZ = TU; a.bZ = TU; a.cZ = UU;
        a.outF = mo;
        tc(2, a, 768, 768, 4);
        comb<4><<<(int)(2*UU/1024), 256>>>(mo, UU, 2, 2*UU, nullptr, kvhi, kvlo);
        a = {}; a.Ahi = qhi; a.Alo = qlo; a.Bhi = kvhi; a.Blo = kvlo;
        a.N = 768; a.K = 768; a.kSplit = 256; a.SK = 3; a.aZ = TU; a.bZ = UU; a.cZ = TU;
        a.outF = mo;
        tc(2, a, T_DIM, 768, 6);
        combA<0><<<BT, 256>>>(mo, den, h, nullptr, nullptr, nullptr,
                              gW + (long)l * U_DIM * E_DIM, gb + l * E_DIM, nullptr,
                              nullptr, nullptr, n, gate, nhi, nlo);
        // moe
        gatemul<<<(int)(BT * 6144 / 256), 256>>>(n, gate, amhi, amlo);
        a = {}; a.Ahi = amhi; a.Alo = amlo;
        a.Bhi = whi + OFF_EW + (long)l * 8 * UU; a.Blo = wlo + OFF_EW + (long)l * 8 * UU;
        a.N = 768; a.K = 6144; a.kSplit = 2048; a.SK = 3; a.cZ = HN; a.outF = mo;
        tc(2, a, BT, 768, 3);
        combA<1><<<BT, 256>>>(mo, nullptr, nullptr, nullptr, nullptr,
                              eb + (long)l * E_DIM * U_DIM, nullptr, nullptr, gate,
                              hM, nullptr, nullptr, nullptr, nhi, nlo);
        // ffn
        a = {}; a.Ahi = nhi; a.Alo = nlo;
        a.Bhi = whi + OFF_F1 + (long)l * UU; a.Blo = wlo + OFF_F1 + (long)l * UU;
        a.N = 768; a.K = 768; a.kSplit = 256; a.SK = 3; a.cZ = HN; a.outF = mo;
        tc(2, a, BT, 768, 3);
        comb<1><<<(int)(HN/1024), 256>>>(mo, HN, 3, HN, fb1 + l * U_DIM, f1hi, f1lo);
        a = {}; a.Ahi = f1hi; a.Alo = f1lo;
        a.Bhi = whi + OFF_F2 + (long)l * UU; a.Blo = wlo + OFF_F2 + (long)l * UU;
        a.N = 768; a.K = 768; a.kSplit = 256; a.SK = 3; a.cZ = HN; a.outF = mo;
        tc(2, a, BT, 768, 3);
        combA<2><<<BT, 256>>>(mo, nullptr, h, hM, fb2 + l * U_DIM, nullptr,
                              nullptr, nullptr, nullptr,
                              nullptr, h, n, nullptr, nhi, nlo);
    }

    // final: n = rms(h) (from combA<2>); hA = n + h0; rms(hA) -> fp16 split; logits
    addk<<<(int)(HN/256), 256>>>(n, h0, hA, (int)HN);
    rms_split<1><<<BT, 256>>>(hA, nhi, nlo);
    a = {}; a.Ahi = nhi; a.Alo = nlo; a.Bhi = whi + OFF_WLOG; a.Blo = wlo + OFF_WLOG;
    a.N = 32000; a.K = 768; a.SK = 1; a.outF = out;
    tc(7, a, BT, 32000, 1);
}

// round 10
// speedup vs baseline: 2.8959x; 1.0468x over previous
#include <cuda_runtime.h>
#include <cuda_bf16.h>
#include <cuda_fp16.h>
#include <cstdint>

#define U_DIM 768
#define T_DIM 1024
#define B_DIM 2
#define BT    2048
#define E_DIM 8
#define L_DIM 16
#define V_DIM 32000
#define EPS_F 1e-6f
#define UU    589824L
#define TU    786432L
#define HN    1572864L

#define OFF_WIN  0L
#define OFF_QKV  (UU)
#define OFF_F1   (OFF_QKV + 48L*UU)
#define OFF_F2   (OFF_F1 + 16L*UU)
#define OFF_EW   (OFF_F2 + 16L*UU)
#define OFF_WLOG (OFF_EW + 128L*UU)
#define W_TOTAL  (OFF_WLOG + 32000L*768L)

typedef __nv_bfloat16 bf16;

__device__ bf16 g_whi[W_TOTAL];
__device__ bf16 g_wlo[W_TOTAL];
__device__ float g_h[HN], g_h0[HN], g_hA[HN], g_hM[HN], g_n[HN];
__device__ float g_mo[3*HN];
__device__ float g_ksum[B_DIM*U_DIM], g_den[BT], g_gate[BT*E_DIM];
__device__ bf16 g_nhi[HN],  g_nlo[HN];
__device__ bf16 g_xhi[HN],  g_xlo[HN];
__device__ bf16 g_qhi[HN],  g_qlo[HN];
__device__ bf16 g_kthi[HN], g_ktlo[HN];
__device__ bf16 g_vthi[HN], g_vtlo[HN];
__device__ bf16 g_kvhi[B_DIM*UU], g_kvlo[B_DIM*UU];
__device__ bf16 g_f1hi[HN], g_f1lo[HN];
__device__ bf16 g_amhi[BT*6144L], g_amlo[BT*6144L];

__device__ __forceinline__ uint32_t smem_u32(const void* p) {
    uint32_t a;
    asm("{ .reg .u64 t; cvta.to.shared.u64 t, %1; cvt.u32.u64 %0, t; }" : "=r"(a) : "l"(p));
    return a;
}
__device__ __forceinline__ void split2(float x, bf16& hi, bf16& lo) {
    hi = __float2bfloat16(x);
    lo = __float2bfloat16(x - __bfloat162float(hi));
}
__device__ __forceinline__ void split2h(float x, __half& hi, __half& lo) {
    hi = __float2half(x);
    lo = __float2half(x - __half2float(hi));
}
__device__ __forceinline__ float warpSum(float v) {
    #pragma unroll
    for (int o = 16; o > 0; o >>= 1) v += __shfl_xor_sync(0xffffffffu, v, o);
    return v;
}

struct GArgs {
    const bf16 *Ahi, *Alo, *Bhi, *Blo;
    int N, K, kSplit, SK;
    long aZ, bZ, cZ;
    const float *bias, *bias2, *bias3;
    float *outF, *outF2;
    bf16 *oHi, *oLo, *oHi2, *oLo2, *oHi3, *oLo3;
};

#define ROWS 72
#define TB   (128 * ROWS * 2)
#define DSM  (12 * TB)         // 3 stages x 4 tiles = 221184

// EPI: 1 out(+copy), 2 partial, 7 logits x2, 8 qkv.  P2: fp16 2-pass (drop A-lo)
template<int EPI, int P2>
__global__ __launch_bounds__(256)
void mma_gemm(GArgs g)
{
    extern __shared__ char smem[];
    uint32_t sb = smem_u32(smem);
    const int tid = threadIdx.x, wid = tid >> 5, lane = tid & 31;
    const int wm = wid >> 2, wn = wid & 3;
    const int z = blockIdx.z;
    const int zB = g.SK > 1 ? z / g.SK : z;
    const int zS = g.SK > 1 ? z % g.SK : 0;
    const int row0 = blockIdx.y * 128, col0 = blockIdx.x * 128;
    const int Nn = g.N, K = g.K;

    const bf16* Ahi = g.Ahi + (long)zB * g.aZ;
    const bf16* Alo = g.Alo + (long)zB * g.aZ;
    const bf16* Bhi = g.Bhi + (long)zB * g.bZ;
    const bf16* Blo = g.Blo + (long)zB * g.bZ;
    const int kbase = g.kSplit ? zS * g.kSplit : 0;
    const int CH = (g.kSplit ? g.kSplit : K) >> 6;

    float d[4][4][4];
    #pragma unroll
    for (int a = 0; a < 4; a++)
        #pragma unroll
        for (int b = 0; b < 4; b++)
            #pragma unroll
            for (int c = 0; c < 4; c++) d[a][b][c] = 0.f;

    auto issue = [&](int c, int s) {
        int k0 = kbase + (c << 6);
        const bf16* srcs[4] = {
            Ahi + (long)row0 * K + k0, Alo + (long)row0 * K + k0,
            Bhi + (long)col0 * K + k0, Blo + (long)col0 * K + k0 };
        #pragma unroll
        for (int t = 0; t < 4; t++) {
            if (P2 && t == 1) continue;
            uint32_t dst = sb + (uint32_t)(s * 4 + t) * TB;
            #pragma unroll
            for (int i = 0; i < 4; i++) {
                int idx = tid + (i << 8);
                int r = idx >> 3, cc = idx & 7;
                uint32_t doff = (uint32_t)(r * ROWS + cc * 8) * 2;
                const void* sp = srcs[t] + (long)r * K + cc * 8;
                asm volatile("cp.async.cg.shared.global [%0], [%1], 16;"
                             :: "r"(dst + doff), "l"(sp));
            }
        }
        asm volatile("cp.async.commit_group;");
    };

    issue(0, 0);
    if (CH > 1) issue(1, 1);
    for (int c = 0; c < CH; c++) {
        int s = c % 3;
        if (c + 2 < CH) { issue(c + 2, (c + 2) % 3); asm volatile("cp.async.wait_group 2;"); }
        else if (c + 1 < CH) { asm volatile("cp.async.wait_group 1;"); }
        else { asm volatile("cp.async.wait_group 0;"); }
        __syncthreads();
        uint32_t bAH = sb + (uint32_t)(s * 4 + 0) * TB;
        uint32_t bAL = sb + (uint32_t)(s * 4 + 1) * TB;
        uint32_t bBH = sb + (uint32_t)(s * 4 + 2) * TB;
        uint32_t bBL = sb + (uint32_t)(s * 4 + 3) * TB;
        #pragma unroll
        for (int ks = 0; ks < 4; ks++) {
            int k16 = ks * 16;
            int aoff = (wm * 64 + (lane & 15)) * ROWS + k16 + ((lane >> 4) << 3);
            int boff = (wn * 32 + (lane & 7)) * ROWS + k16 + (((lane >> 3) & 1) << 3);
            uint32_t af[4][4], af2[4][4], bf_[4][2];
            #pragma unroll
            for (int mt = 0; mt < 4; mt++) {
                uint32_t ad = bAH + (uint32_t)(aoff + mt * 16 * ROWS) * 2;
                asm volatile("ldmatrix.sync.aligned.m8n8.x4.shared.b16 {%0,%1,%2,%3}, [%4];"
                    : "=r"(af[mt][0]), "=r"(af[mt][1]), "=r"(af[mt][2]), "=r"(af[mt][3]) : "r"(ad));
            }
            #pragma unroll
            for (int nt = 0; nt < 4; nt++) {
                uint32_t bd = bBH + (uint32_t)(boff + nt * 8 * ROWS) * 2;
                asm volatile("ldmatrix.sync.aligned.m8n8.x2.shared.b16 {%0,%1}, [%2];"
                    : "=r"(bf_[nt][0]), "=r"(bf_[nt][1]) : "r"(bd));
            }
            #pragma unroll
            for (int mt = 0; mt < 4; mt++)
                #pragma unroll
                for (int nt = 0; nt < 4; nt++) {
                    if (P2)
                        asm volatile("mma.sync.aligned.m16n8k16.row.col.f32.f16.f16.f32 "
                            "{%0,%1,%2,%3}, {%4,%5,%6,%7}, {%8,%9}, {%0,%1,%2,%3};"
                            : "+f"(d[mt][nt][0]), "+f"(d[mt][nt][1]), "+f"(d[mt][nt][2]), "+f"(d[mt][nt][3])
                            : "r"(af[mt][0]), "r"(af[mt][1]), "r"(af[mt][2]), "r"(af[mt][3]),
                              "r"(bf_[nt][0]), "r"(bf_[nt][1]));
                    else
                        asm volatile("mma.sync.aligned.m16n8k16.row.col.f32.bf16.bf16.f32 "
                            "{%0,%1,%2,%3}, {%4,%5,%6,%7}, {%8,%9}, {%0,%1,%2,%3};"
                            : "+f"(d[mt][nt][0]), "+f"(d[mt][nt][1]), "+f"(d[mt][nt][2]), "+f"(d[mt][nt][3])
                            : "r"(af[mt][0]), "r"(af[mt][1]), "r"(af[mt][2]), "r"(af[mt][3]),
                              "r"(bf_[nt][0]), "r"(bf_[nt][1]));
                }
            if (!P2) {
                #pragma unroll
                for (int mt = 0; mt < 4; mt++) {
                    uint32_t ad = bAL + (uint32_t)(aoff + mt * 16 * ROWS) * 2;
                    asm volatile("ldmatrix.sync.aligned.m8n8.x4.shared.b16 {%0,%1,%2,%3}, [%4];"
                        : "=r"(af2[mt][0]), "=r"(af2[mt][1]), "=r"(af2[mt][2]), "=r"(af2[mt][3]) : "r"(ad));
                }
                #pragma unroll
                for (int mt = 0; mt < 4; mt++)
                    #pragma unroll
                    for (int nt = 0; nt < 4; nt++)
                        asm volatile("mma.sync.aligned.m16n8k16.row.col.f32.bf16.bf16.f32 "
                            "{%0,%1,%2,%3}, {%4,%5,%6,%7}, {%8,%9}, {%0,%1,%2,%3};"
                            : "+f"(d[mt][nt][0]), "+f"(d[mt][nt][1]), "+f"(d[mt][nt][2]), "+f"(d[mt][nt][3])
                            : "r"(af2[mt][0]), "r"(af2[mt][1]), "r"(af2[mt][2]), "r"(af2[mt][3]),
                              "r"(bf_[nt][0]), "r"(bf_[nt][1]));
            }
            #pragma unroll
            for (int nt = 0; nt < 4; nt++) {
                uint32_t bd = bBL + (uint32_t)(boff + nt * 8 * ROWS) * 2;
                asm volatile("ldmatrix.sync.aligned.m8n8.x2.shared.b16 {%0,%1}, [%2];"
                    : "=r"(bf_[nt][0]), "=r"(bf_[nt][1]) : "r"(bd));
            }
            #pragma unroll
            for (int mt = 0; mt < 4; mt++)
                #pragma unroll
                for (int nt = 0; nt < 4; nt++) {
                    if (P2)
                        asm volatile("mma.sync.aligned.m16n8k16.row.col.f32.f16.f16.f32 "
                            "{%0,%1,%2,%3}, {%4,%5,%6,%7}, {%8,%9}, {%0,%1,%2,%3};"
                            : "+f"(d[mt][nt][0]), "+f"(d[mt][nt][1]), "+f"(d[mt][nt][2]), "+f"(d[mt][nt][3])
                            : "r"(af[mt][0]), "r"(af[mt][1]), "r"(af[mt][2]), "r"(af[mt][3]),
                              "r"(bf_[nt][0]), "r"(bf_[nt][1]));
                    else
                        asm volatile("mma.sync.aligned.m16n8k16.row.col.f32.bf16.bf16.f32 "
                            "{%0,%1,%2,%3}, {%4,%5,%6,%7}, {%8,%9}, {%0,%1,%2,%3};"
                            : "+f"(d[mt][nt][0]), "+f"(d[mt][nt][1]), "+f"(d[mt][nt][2]), "+f"(d[mt][nt][3])
                            : "r"(af[mt][0]), "r"(af[mt][1]), "r"(af[mt][2]), "r"(af[mt][3]),
                              "r"(bf_[nt][0]), "r"(bf_[nt][1]));
                }
        }
        __syncthreads();
    }

    // ---------------- epilogues ----------------
    if (EPI == 8) {
        const int blkN = col0 / 768;
        const int cc0  = col0 - blkN * 768;
        if (blkN == 0) {
            #pragma unroll
            for (int mt = 0; mt < 4; mt++)
                #pragma unroll
                for (int half = 0; half < 2; half++) {
                    int rg = row0 + wm * 64 + mt * 16 + (lane >> 2) + half * 8;
                    #pragma unroll
                    for (int nt = 0; nt < 4; nt++) {
                        int col = cc0 + wn * 32 + nt * 8 + 2 * (lane & 3);
                        float t0 = d[mt][nt][half*2+0] + __ldg(&g.bias[col]);
                        float t1 = d[mt][nt][half*2+1] + __ldg(&g.bias[col+1]);
                        float o0 = (t0 > 0.f) ? (t0 + 1.f) : __expf(t0);
                        float o1 = (t1 > 0.f) ? (t1 + 1.f) : __expf(t1);
                        bf16 h0b,l0b,h1b,l1b; split2(o0,h0b,l0b); split2(o1,h1b,l1b);
                        __nv_bfloat162 ph; ph.x=h0b; ph.y=h1b;
                        __nv_bfloat162 pl; pl.x=l0b; pl.y=l1b;
                        long idx = (long)rg * 768 + col;
                        *(__nv_bfloat162*)(g.oHi + idx) = ph;
                        *(__nv_bfloat162*)(g.oLo + idx) = pl;
                    }
                }
        } else {
            const float* bp = (blkN == 1) ? g.bias2 : g.bias3;
            float* tile = (float*)smem;
            #pragma unroll
            for (int mt = 0; mt < 4; mt++)
                #pragma unroll
                for (int nt = 0; nt < 4; nt++)
                    #pragma unroll
                    for (int half = 0; half < 2; half++)
                        #pragma unroll
                        for (int jj = 0; jj < 2; jj++) {
                            int r = wm*64 + mt*16 + (lane>>2) + half*8;
                            int cl = wn*32 + nt*8 + 2*(lane&3) + jj;
                            float t = d[mt][nt][half*2+jj] + __ldg(&bp[cc0 + cl]);
                            if (blkN == 1) t = (t > 0.f) ? (t + 1.f) : __expf(t);
                            tile[r * 130 + cl] = t;
                        }
            __syncthreads();
            bf16* dh = (blkN == 1) ? g.oHi2 : g.oHi3;
            bf16* dl = (blkN == 1) ? g.oLo2 : g.oLo3;
            int u_l = tid & 127, th = tid >> 7;
            int bb = row0 >> 10, t0 = row0 & 1023;
            long rowbase = ((long)(bb * 768 + cc0 + u_l)) * 1024 + t0 + th * 64;
            uint32_t hb[32], lb[32];
            #pragma unroll
            for (int j = 0; j < 64; j += 2) {
                float v0 = tile[(th*64 + j) * 130 + u_l];
                float v1 = tile[(th*64 + j + 1) * 130 + u_l];
                bf16 h0b,l0b,h1b,l1b; split2(v0,h0b,l0b); split2(v1,h1b,l1b);
                __nv_bfloat162 ph; ph.x=h0b; ph.y=h1b;
                __nv_bfloat162 pl; pl.x=l0b; pl.y=l1b;
                hb[j>>1] = *(uint32_t*)&ph; lb[j>>1] = *(uint32_t*)&pl;
            }
            uint4* dh4 = (uint4*)(dh + rowbase);
            uint4* dl4 = (uint4*)(dl + rowbase);
            #pragma unroll
            for (int i = 0; i < 8; i++) { dh4[i] = ((uint4*)hb)[i]; dl4[i] = ((uint4*)lb)[i]; }
        }
        return;
    }

    float* outF = g.outF + (long)z * g.cZ;
    #pragma unroll
    for (int mt = 0; mt < 4; mt++)
        #pragma unroll
        for (int half = 0; half < 2; half++) {
            int rg = row0 + wm * 64 + mt * 16 + (lane >> 2) + half * 8;
            #pragma unroll
            for (int nt = 0; nt < 4; nt++) {
                int col = col0 + wn * 32 + nt * 8 + 2 * (lane & 3);
                #pragma unroll
                for (int jj = 0; jj < 2; jj++) {
                    float x = d[mt][nt][half*2+jj];
                    long idx = (long)rg * Nn + col + jj;
                    if (EPI == 2) outF[idx] = x;
                    else if (EPI == 7) outF[idx] = x * 2.0f;
                    else { outF[idx] = x; if (g.outF2) g.outF2[idx] = x; }
                }
            }
        }
}

// ---------- row-fused combines ----------
// MODE 0: attn -> gate + gated am split (gatemul fused)
// MODE 1: moe (+gate*eb) -> hM, nhi, nlo
// MODE 2: ffn2 sigmoid + hM + h -> h, n, nhi, nlo
template<int MODE>
__global__ __launch_bounds__(256)
void combA(const float* __restrict__ mo, const float* __restrict__ den,
           const float* __restrict__ hOld, const float* __restrict__ hMin,
           const float* __restrict__ bias, const float* __restrict__ eb,
           const float* __restrict__ gWl, const float* __restrict__ gbl,
           const float* __restrict__ gateIn,
           float* hMout, float* hOut, float* nOut, float* gateOut,
           bf16* nhi, bf16* nlo, bf16* amhi, bf16* amlo)
{
    __shared__ float row[768];
    __shared__ float red[8]; __shared__ float rsh; __shared__ float gsl[8][8];
    __shared__ float gfin[8];
    int r = blockIdx.x, tid = threadIdx.x;
    int wid = tid >> 5, lane = tid & 31;
    int b = r >> 10, t = r & 1023;
    for (int u = tid; u < 768; u += 256) {
        float v;
        if (MODE == 0) {
            long base = (long)(b * 3) * TU + (long)t * 768 + u;
            v = mo[base] + mo[base + TU] + mo[base + 2 * TU];
            v = v / den[r] + hOld[(long)r * 768 + u];
        } else {
            long base = (long)r * 768 + u;
            v = mo[base] + mo[base + HN] + mo[base + 2 * HN];
            if (MODE == 1) {
                float bm = 0.f;
                #pragma unroll
                for (int e = 0; e < 8; e++)
                    bm = fmaf(gateIn[(long)r * 8 + e], __ldg(&eb[e * 768 + u]), bm);
                v += bm;
                hMout[base] = v;
            } else {
                float tt = v + __ldg(&bias[u]);
                v = 1.f / (1.f + __expf(-tt)) + hMin[base] + hOld[base];
                hOut[base] = v;
            }
        }
        row[u] = v;
    }
    __syncthreads();
    float s = 0.f;
    for (int u = tid; u < 768; u += 256) { float x = row[u]; s = fmaf(x, x, s); }
    s = warpSum(s);
    if (lane == 0) red[wid] = s;
    __syncthreads();
    if (tid == 0) {
        float tot = 0.f;
        #pragma unroll
        for (int i = 0; i < 8; i++) tot += red[i];
        rsh = rsqrtf(tot / 768.f + EPS_F);
    }
    __syncthreads();
    float rr = rsh;
    if (MODE != 0) {
        for (int u = tid; u < 768; u += 256) {
            float o = row[u] * rr;
            if (MODE == 2) nOut[(long)r * 768 + u] = o;
            bf16 hi, lo; split2(o, hi, lo);
            nhi[(long)r * 768 + u] = hi; nlo[(long)r * 768 + u] = lo;
        }
        return;
    }
    // MODE 0: gate softmax then fused gatemul
    float ge[8];
    #pragma unroll
    for (int e = 0; e < 8; e++) ge[e] = 0.f;
    for (int u = tid; u < 768; u += 256) {
        float o = row[u] * rr;
        #pragma unroll
        for (int e = 0; e < 8; e++) ge[e] = fmaf(o, __ldg(&gWl[u * 8 + e]), ge[e]);
    }
    #pragma unroll
    for (int e = 0; e < 8; e++) ge[e] = warpSum(ge[e]);
    if (lane < 8) gsl[wid][lane] = ge[lane];
    __syncthreads();
    if (tid == 0) {
        float sl[8];
        #pragma unroll
        for (int e = 0; e < 8; e++) {
            float tt = gbl[e];
            #pragma unroll
            for (int w = 0; w < 8; w++) tt += gsl[w][e];
            sl[e] = tt;
        }
        float mx = sl[0];
        #pragma unroll
        for (int e = 1; e < 8; e++) mx = fmaxf(mx, sl[e]);
        float ex[8], sum = 0.f;
        #pragma unroll
        for (int e = 0; e < 8; e++) { ex[e] = __expf(sl[e] - mx); sum += ex[e]; }
        float inv = 1.f / sum;
        #pragma unroll
        for (int e = 0; e < 8; e++) { float gv = ex[e] * inv; gfin[e] = gv; gateOut[(long)r * 8 + e] = gv; }
    }
    __syncthreads();
    long abase = (long)r * 6144;
    for (int i = tid; i < 3072; i += 256) {
        int e = i / 384, u2 = (i % 384) * 2;
        float gv = gfin[e];
        float o0 = row[u2] * rr * gv, o1 = row[u2 + 1] * rr * gv;
        bf16 h0b,l0b,h1b,l1b; split2(o0,h0b,l0b); split2(o1,h1b,l1b);
        __nv_bfloat162 ph; ph.x=h0b; ph.y=h1b;
        __nv_bfloat162 pl; pl.x=l0b; pl.y=l1b;
        *(__nv_bfloat162*)(amhi + abase + e * 768 + u2) = ph;
        *(__nv_bfloat162*)(amlo + abase + e * 768 + u2) = pl;
    }
}

// elementwise combines: MODE 1 f1-sig-split, MODE 4 kv-split
template<int MODE>
__global__ __launch_bounds__(256)
void comb(const float* __restrict__ p, long segZ, int ns, long total,
          const float* __restrict__ bias, bf16* oHi, bf16* oLo)
{
    long i4 = ((long)blockIdx.x * 256 + threadIdx.x) * 4;
    if (i4 >= total) return;
    long base = (i4 / segZ) * (long)ns * segZ + (i4 % segZ);
    float4 s = *(const float4*)(p + base);
    float4 s1 = *(const float4*)(p + base + segZ);
    s.x += s1.x; s.y += s1.y; s.z += s1.z; s.w += s1.w;
    if (ns == 3) {
        float4 s2 = *(const float4*)(p + base + 2 * segZ);
        s.x += s2.x; s.y += s2.y; s.z += s2.z; s.w += s2.w;
    }
    float v[4] = {s.x, s.y, s.z, s.w};
    int col = (int)(i4 % 768);
    bf16 hh[4], ll[4];
    #pragma unroll
    for (int j = 0; j < 4; j++) {
        float o = v[j];
        if (MODE == 1) { float t = o + __ldg(&bias[col + j]); o = 1.f / (1.f + __expf(-t)); }
        split2(o, hh[j], ll[j]);
    }
    *(uint2*)(oHi + i4) = *(uint2*)hh;
    *(uint2*)(oLo + i4) = *(uint2*)ll;
}

// ---------- prepack ----------
__global__ __launch_bounds__(256)
void tsplit(const float* __restrict__ src, bf16* dhi, bf16* dlo, int K, int N,
            int mode, long outZ, long rowOff)
{
    __shared__ float t[32][33];
    int z = blockIdx.z;
    const float* s = src + (long)z * K * N;
    long dbase; int dld;
    if (mode == 1) { int l = z >> 3, e = z & 7; dbase = (long)l * 8 * UU + (long)e * U_DIM; dld = 6144; }
    else { dbase = (long)z * outZ + rowOff; dld = K; }
    int n0 = blockIdx.x * 32, k0 = blockIdx.y * 32;
    int tx = threadIdx.x & 31, ty = threadIdx.x >> 5;
    #pragma unroll
    for (int i = 0; i < 32; i += 8) t[ty + i][tx] = s[(long)(k0 + ty + i) * N + n0 + tx];
    __syncthreads();
    #pragma unroll
    for (int i = 0; i < 32; i += 8) {
        float v = t[tx][ty + i];
        long di = dbase + (long)(n0 + ty + i) * dld + k0 + tx;
        if (mode == 2) {
            __half hi, lo; split2h(v, hi, lo);
            ((__half*)dhi)[di] = hi; ((__half*)dlo)[di] = lo;
        } else {
            bf16 hi, lo; split2(v, hi, lo);
            dhi[di] = hi; dlo[di] = lo;
        }
    }
}

// ---------- small kernels ----------
__global__ __launch_bounds__(192)
void gather_split(const int* __restrict__ x, const float* __restrict__ emb, bf16* xhi, bf16* xlo)
{
    int row = blockIdx.x, tok = x[row];
    const float* s = emb + (long)tok * U_DIM;
    for (int i = threadIdx.x; i < U_DIM; i += 192) {
        bf16 hi, lo; split2(s[i], hi, lo);
        xhi[(long)row * U_DIM + i] = hi; xlo[(long)row * U_DIM + i] = lo;
    }
}
template<int HALF>
__global__ __launch_bounds__(256)
void rms_split(const float* __restrict__ h, bf16* nhi, bf16* nlo)
{
    long row = blockIdx.x;
    const float* hr = h + row * U_DIM;
    float s = 0.f;
    for (int u = threadIdx.x; u < U_DIM; u += 256) { float t = hr[u]; s = fmaf(t, t, s); }
    s = warpSum(s);
    __shared__ float red[8]; __shared__ float rsh;
    int wid = threadIdx.x >> 5, lane = threadIdx.x & 31;
    if (lane == 0) red[wid] = s;
    __syncthreads();
    if (threadIdx.x == 0) {
        float tot = 0.f;
        #pragma unroll
        for (int i = 0; i < 8; i++) tot += red[i];
        rsh = rsqrtf(tot / (float)U_DIM + EPS_F);
    }
    __syncthreads();
    float r = rsh;
    for (int u = threadIdx.x; u < U_DIM; u += 256) {
        float o = hr[u] * r;
        if (HALF) {
            __half hi, lo; split2h(o, hi, lo);
            ((__half*)nhi)[row * U_DIM + u] = hi;
            ((__half*)nlo)[row * U_DIM + u] = lo;
        } else {
            bf16 hi, lo; split2(o, hi, lo);
            nhi[row * U_DIM + u] = hi; nlo[row * U_DIM + u] = lo;
        }
    }
}
__global__ __launch_bounds__(256)
void colsum(const bf16* __restrict__ khi, const bf16* __restrict__ klo, float* ks)
{
    int gw = blockIdx.x * 8 + (threadIdx.x >> 5);
    int lane = threadIdx.x & 31;
    const bf16* ph = khi + (long)gw * 1024;
    const bf16* pl = klo + (long)gw * 1024;
    float s = 0.f;
    for (int t = lane; t < 1024; t += 32)
        s += __bfloat162float(ph[t]) + __bfloat162float(pl[t]);
    s = warpSum(s);
    if (lane == 0) ks[gw] = s;
}
__global__ __launch_bounds__(256)
void denk(const bf16* __restrict__ qhi, const bf16* __restrict__ qlo,
          const float* __restrict__ ks, float* den)
{
    int gw = (blockIdx.x * 256 + threadIdx.x) >> 5;
    int lane = threadIdx.x & 31;
    if (gw >= BT) return;
    int b = gw >> 10;
    const bf16* ph = qhi + (long)gw * U_DIM;
    const bf16* pl = qlo + (long)gw * U_DIM;
    const float* kb = ks + b * U_DIM;
    float s = 0.f;
    for (int u = lane; u < U_DIM; u += 32)
        s = fmaf(__bfloat162float(ph[u]) + __bfloat162float(pl[u]), kb[u], s);
    s = warpSum(s);
    if (lane == 0) den[gw] = s + EPS_F;
}
__global__ __launch_bounds__(256)
void addk(const float* __restrict__ a, const float* __restrict__ b, float* c, int n)
{
    int i = blockIdx.x * 256 + threadIdx.x;
    if (i < n) c[i] = a[i] + b[i];
}

// ---------- host ----------
static void tc(int epi, GArgs& a, int M, int N, int Z)
{
    dim3 g(N / 128, M / 128, Z);
    switch (epi) {
    case 1: mma_gemm<1,0><<<g, 256, DSM>>>(a); break;
    case 2: mma_gemm<2,0><<<g, 256, DSM>>>(a); break;
    case 7: mma_gemm<7,1><<<g, 256, DSM>>>(a); break;
    case 8: mma_gemm<8,0><<<g, 256, DSM>>>(a); break;
    }
}

extern "C" void kernel_launch(void* const* d_in, const int* in_sizes, int n_in,
                              void* d_out, int out_size)
{
    const int*   x    = (const int*)  d_in[0];
    const float* emb  = (const float*)d_in[1];
    const float* W_in = (const float*)d_in[2];
    const float* Wq   = (const float*)d_in[3];
    const float* bq   = (const float*)d_in[4];
    const float* Wk   = (const float*)d_in[5];
    const float* bk   = (const float*)d_in[6];
    const float* Wv   = (const float*)d_in[7];
    const float* bv   = (const float*)d_in[8];
    const float* gW   = (const float*)d_in[9];
    const float* gb   = (const float*)d_in[10];
    const float* eW   = (const float*)d_in[11];
    const float* eb   = (const float*)d_in[12];
    const float* fW1  = (const float*)d_in[13];
    const float* fb1  = (const float*)d_in[14];
    const float* fW2  = (const float*)d_in[15];
    const float* fb2  = (const float*)d_in[16];
    const float* Wlog = (const float*)d_in[17];
    float* out = (float*)d_out;

    cudaFuncSetAttribute((const void*)mma_gemm<1,0>, cudaFuncAttributeMaxDynamicSharedMemorySize, DSM);
    cudaFuncSetAttribute((const void*)mma_gemm<2,0>, cudaFuncAttributeMaxDynamicSharedMemorySize, DSM);
    cudaFuncSetAttribute((const void*)mma_gemm<7,1>, cudaFuncAttributeMaxDynamicSharedMemorySize, DSM);
    cudaFuncSetAttribute((const void*)mma_gemm<8,0>, cudaFuncAttributeMaxDynamicSharedMemorySize, DSM);

    bf16 *whi, *wlo, *nhi, *nlo, *xhi, *xlo, *qhi, *qlo, *kthi, *ktlo, *vthi, *vtlo;
    bf16 *kvhi, *kvlo, *f1hi, *f1lo, *amhi, *amlo;
    float *h, *h0, *hA, *hM, *n, *mo, *ksum, *den, *gate;
    cudaGetSymbolAddress((void**)&whi, g_whi);  cudaGetSymbolAddress((void**)&wlo, g_wlo);
    cudaGetSymbolAddress((void**)&h, g_h);      cudaGetSymbolAddress((void**)&h0, g_h0);
    cudaGetSymbolAddress((void**)&hA, g_hA);    cudaGetSymbolAddress((void**)&hM, g_hM);
    cudaGetSymbolAddress((void**)&n, g_n);      cudaGetSymbolAddress((void**)&mo, g_mo);
    cudaGetSymbolAddress((void**)&ksum, g_ksum);
    cudaGetSymbolAddress((void**)&den, g_den);  cudaGetSymbolAddress((void**)&gate, g_gate);
    cudaGetSymbolAddress((void**)&nhi, g_nhi);  cudaGetSymbolAddress((void**)&nlo, g_nlo);
    cudaGetSymbolAddress((void**)&xhi, g_xhi);  cudaGetSymbolAddress((void**)&xlo, g_xlo);
    cudaGetSymbolAddress((void**)&qhi, g_qhi);  cudaGetSymbolAddress((void**)&qlo, g_qlo);
    cudaGetSymbolAddress((void**)&kthi, g_kthi); cudaGetSymbolAddress((void**)&ktlo, g_ktlo);
    cudaGetSymbolAddress((void**)&vthi, g_vthi); cudaGetSymbolAddress((void**)&vtlo, g_vtlo);
    cudaGetSymbolAddress((void**)&kvhi, g_kvhi); cudaGetSymbolAddress((void**)&kvlo, g_kvlo);
    cudaGetSymbolAddress((void**)&f1hi, g_f1hi); cudaGetSymbolAddress((void**)&f1lo, g_f1lo);
    cudaGetSymbolAddress((void**)&amhi, g_amhi); cudaGetSymbolAddress((void**)&amlo, g_amlo);

    GArgs a;
    // ncu capture lands on 0-based launch #3 -> make it the h0 GEMM
    tsplit<<<dim3(24, 24, 1),   256>>>(W_in, whi + OFF_WIN, wlo + OFF_WIN, 768, 768, 0, UU, 0);   // 0
    gather_split<<<BT, 192>>>(x, emb, xhi, xlo);                                                   // 1
    tsplit<<<dim3(24, 24, 16),  256>>>(Wq, whi + OFF_QKV, wlo + OFF_QKV, 768, 768, 0, 3*UU, 0);   // 2
    a = {}; a.Ahi = xhi; a.Alo = xlo; a.Bhi = whi + OFF_WIN; a.Blo = wlo + OFF_WIN;
    a.N = 768; a.K = 768; a.SK = 1; a.outF = h0; a.outF2 = h;
    tc(1, a, BT, 768, 1);                                                                          // 3 <- ncu
    tsplit<<<dim3(24, 24, 16),  256>>>(Wk, whi + OFF_QKV, wlo + OFF_QKV, 768, 768, 0, 3*UU, UU);
    tsplit<<<dim3(24, 24, 16),  256>>>(Wv, whi + OFF_QKV, wlo + OFF_QKV, 768, 768, 0, 3*UU, 2*UU);
    tsplit<<<dim3(24, 24, 16),  256>>>(fW1, whi + OFF_F1, wlo + OFF_F1, 768, 768, 0, UU, 0);
    tsplit<<<dim3(24, 24, 16),  256>>>(fW2, whi + OFF_F2, wlo + OFF_F2, 768, 768, 0, UU, 0);
    tsplit<<<dim3(24, 24, 128), 256>>>(eW, whi + OFF_EW, wlo + OFF_EW, 768, 768, 1, 0, 0);
    tsplit<<<dim3(1000, 24, 1), 256>>>(Wlog, whi + OFF_WLOG, wlo + OFF_WLOG, 768, 32000, 2, 0, 0);
    rms_split<0><<<BT, 256>>>(h, nhi, nlo);

    for (int l = 0; l < L_DIM; l++) {
        // attention
        a = {}; a.Ahi = nhi; a.Alo = nlo;
        a.Bhi = whi + OFF_QKV + (long)l * 3 * UU; a.Blo = wlo + OFF_QKV + (long)l * 3 * UU;
        a.N = 2304; a.K = 768; a.SK = 1;
        a.bias = bq + l * U_DIM; a.bias2 = bk + l * U_DIM; a.bias3 = bv + l * U_DIM;
        a.oHi = qhi; a.oLo = qlo; a.oHi2 = kthi; a.oLo2 = ktlo; a.oHi3 = vthi; a.oLo3 = vtlo;
        tc(8, a, BT, 2304, 1);
        colsum<<<192, 256>>>(kthi, ktlo, ksum);
        denk<<<256, 256>>>(qhi, qlo, ksum, den);
        a = {}; a.Ahi = vthi; a.Alo = vtlo; a.Bhi = kthi; a.Blo = ktlo;
        a.N = 768; a.K = 1024; a.kSplit = 512; a.SK = 2; a.aZ = TU; a.bZ = TU; a.cZ = UU;
        a.outF = mo;
        tc(2, a, 768, 768, 4);
        comb<4><<<(int)(2*UU/1024), 256>>>(mo, UU, 2, 2*UU, nullptr, kvhi, kvlo);
        a = {}; a.Ahi = qhi; a.Alo = qlo; a.Bhi = kvhi; a.Blo = kvlo;
        a.N = 768; a.K = 768; a.kSplit = 256; a.SK = 3; a.aZ = TU; a.bZ = UU; a.cZ = TU;
        a.outF = mo;
        tc(2, a, T_DIM, 768, 6);
        combA<0><<<BT, 256>>>(mo, den, h, nullptr, nullptr, nullptr,
                              gW + (long)l * U_DIM * E_DIM, gb + l * E_DIM, nullptr,
                              nullptr, nullptr, nullptr, gate, nullptr, nullptr, amhi, amlo);
        // moe
        a = {}; a.Ahi = amhi; a.Alo = amlo;
        a.Bhi = whi + OFF_EW + (long)l * 8 * UU; a.Blo = wlo + OFF_EW + (long)l * 8 * UU;
        a.N = 768; a.K = 6144; a.kSplit = 2048; a.SK = 3; a.cZ = HN; a.outF = mo;
        tc(2, a, BT, 768, 3);
        combA<1><<<BT, 256>>>(mo, nullptr, nullptr, nullptr, nullptr,
                              eb + (long)l * E_DIM * U_DIM, nullptr, nullptr, gate,
                              hM, nullptr, nullptr, nullptr, nhi, nlo, nullptr, nullptr);
        // ffn
        a = {}; a.Ahi = nhi; a.Alo = nlo;
        a.Bhi = whi + OFF_F1 + (long)l * UU; a.Blo = wlo + OFF_F1 + (long)l * UU;
        a.N = 768; a.K = 768; a.kSplit = 256; a.SK = 3; a.cZ = HN; a.outF = mo;
        tc(2, a, BT, 768, 3);
        comb<1><<<(int)(HN/1024), 256>>>(mo, HN, 3, HN, fb1 + l * U_DIM, f1hi, f1lo);
        a = {}; a.Ahi = f1hi; a.Alo = f1lo;
        a.Bhi = whi + OFF_F2 + (long)l * UU; a.Blo = wlo + OFF_F2 + (long)l * UU;
        a.N = 768; a.K = 768; a.kSplit = 256; a.SK = 3; a.cZ = HN; a.outF = mo;
        tc(2, a, BT, 768, 3);
        combA<2><<<BT, 256>>>(mo, nullptr, h, hM, fb2 + l * U_DIM, nullptr,
                              nullptr, nullptr, nullptr,
                              nullptr, h, n, nullptr, nhi, nlo, nullptr, nullptr);
    }

    // final: n = rms(h); hA = n + h0; rms(hA) -> fp16 split; logits
    addk<<<(int)(HN/256), 256>>>(n, h0, hA, (int)HN);
    rms_split<1><<<BT, 256>>>(hA, nhi, nlo);
    a = {}; a.Ahi = nhi; a.Alo = nlo; a.Bhi = whi + OFF_WLOG; a.Blo = wlo + OFF_WLOG;
    a.N = 32000; a.K = 768; a.SK = 1; a.outF = out;
    tc(7, a, BT, 32000, 1);
}